// round 1
// baseline (speedup 1.0000x reference)
#include <cuda_runtime.h>
#include <math.h>

#define S_LEN   4096
#define D_MODEL 2048
#define NHEADS  16
#define HDIM    128

// Scratch (device globals: allocation-guard-safe)
__device__ float g_q[S_LEN * D_MODEL];
__device__ float g_k[S_LEN * D_MODEL];
__device__ float g_v[S_LEN * D_MODEL];
__device__ float g_o[S_LEN * D_MODEL];

// ---------------------------------------------------------------------------
// GEMM (NT): C[m,n] = sum_k A[m,k] * B[n,k]
// BM=BN=128, BK=16, 256 threads, 8x8 micro-tile per thread.
// blockIdx.z selects (B,C) pair so QKV runs as one launch.
// ---------------------------------------------------------------------------
#define BM 128
#define BN 128
#define BKT 16

__global__ __launch_bounds__(256) void gemm_nt_kernel(
    const float* __restrict__ A,
    const float* __restrict__ B0, const float* __restrict__ B1, const float* __restrict__ B2,
    float* __restrict__ C0, float* __restrict__ C1, float* __restrict__ C2,
    int M, int N, int K)
{
    const float* B = (blockIdx.z == 0) ? B0 : (blockIdx.z == 1) ? B1 : B2;
    float*       C = (blockIdx.z == 0) ? C0 : (blockIdx.z == 1) ? C1 : C2;

    __shared__ float As[BKT][BM];
    __shared__ float Bs[BKT][BN];

    const int tid = threadIdx.x;
    const int m0 = blockIdx.y * BM;
    const int n0 = blockIdx.x * BN;
    const int tm = tid >> 4;   // 0..15
    const int tn = tid & 15;   // 0..15

    float acc[8][8];
#pragma unroll
    for (int i = 0; i < 8; i++)
#pragma unroll
        for (int j = 0; j < 8; j++) acc[i][j] = 0.0f;

    for (int k0 = 0; k0 < K; k0 += BKT) {
        // Load A-tile and B-tile (transposed into smem). 512 float4 each.
#pragma unroll
        for (int i = 0; i < 2; i++) {
            int f  = tid + i * 256;
            int m  = f >> 2;          // 0..127
            int kc = (f & 3) << 2;    // 0,4,8,12
            float4 va = *(const float4*)(A + (size_t)(m0 + m) * K + k0 + kc);
            As[kc + 0][m] = va.x; As[kc + 1][m] = va.y;
            As[kc + 2][m] = va.z; As[kc + 3][m] = va.w;
            float4 vb = *(const float4*)(B + (size_t)(n0 + m) * K + k0 + kc);
            Bs[kc + 0][m] = vb.x; Bs[kc + 1][m] = vb.y;
            Bs[kc + 2][m] = vb.z; Bs[kc + 3][m] = vb.w;
        }
        __syncthreads();

#pragma unroll
        for (int kk = 0; kk < BKT; kk++) {
            float a[8], b[8];
            *(float4*)&a[0] = *(const float4*)&As[kk][tm * 8];
            *(float4*)&a[4] = *(const float4*)&As[kk][tm * 8 + 4];
            *(float4*)&b[0] = *(const float4*)&Bs[kk][tn * 8];
            *(float4*)&b[4] = *(const float4*)&Bs[kk][tn * 8 + 4];
#pragma unroll
            for (int i = 0; i < 8; i++)
#pragma unroll
                for (int j = 0; j < 8; j++)
                    acc[i][j] = fmaf(a[i], b[j], acc[i][j]);
        }
        __syncthreads();
    }

#pragma unroll
    for (int i = 0; i < 8; i++) {
        float4 v0 = make_float4(acc[i][0], acc[i][1], acc[i][2], acc[i][3]);
        float4 v1 = make_float4(acc[i][4], acc[i][5], acc[i][6], acc[i][7]);
        float* crow = C + (size_t)(m0 + tm * 8 + i) * N + n0 + tn * 8;
        *(float4*)(crow)     = v0;
        *(float4*)(crow + 4) = v1;
    }
}

// ---------------------------------------------------------------------------
// Flash attention, fp32, causal. One CTA = (head, 128-row q-block).
// BQ=128 query rows, BKV=64 key rows per iteration, Dh=128.
// Padded smem strides to avoid stride-128 bank conflicts.
// ---------------------------------------------------------------------------
#define BQ   128
#define BKV  64
#define QSTR 132   // Q/K row stride (floats): 16B-aligned, 132 % 32 == 4
#define VSTR 128
#define SSTR 68    // 16B-aligned, 68 % 32 == 4

__global__ __launch_bounds__(256) void attn_kernel(const int* __restrict__ causal_flag)
{
    extern __shared__ float smem[];
    float* Qs   = smem;                       // BQ  * QSTR
    float* Ks   = Qs  + BQ * QSTR;            // BKV * QSTR
    float* Vs   = Ks  + BKV * QSTR;           // BKV * VSTR
    float* Ss   = Vs  + BKV * VSTR;           // BQ  * SSTR
    float* m_s  = Ss  + BQ * SSTR;            // BQ
    float* l_s  = m_s + BQ;                   // BQ
    float* al_s = l_s + BQ;                   // BQ

    const int tid = threadIdx.x;
    const int qb  = blockIdx.x;
    const int h   = blockIdx.y;
    const int q0  = qb * BQ;
    const int causal = *causal_flag;
    const float sm_scale = 0.08838834764831845f;  // 1/sqrt(128)

    // Load Q block: 128x128 floats = 4096 float4 (16 per thread)
#pragma unroll
    for (int i = 0; i < 16; i++) {
        int f  = tid + i * 256;
        int r  = f >> 5;
        int c4 = (f & 31) << 2;
        float4 v = *(const float4*)(g_q + (size_t)(q0 + r) * D_MODEL + h * HDIM + c4);
        *(float4*)&Qs[r * QSTR + c4] = v;
    }
    if (tid < BQ) { m_s[tid] = -1e30f; l_s[tid] = 0.0f; }

    float o[8][8];
#pragma unroll
    for (int i = 0; i < 8; i++)
#pragma unroll
        for (int j = 0; j < 8; j++) o[i][j] = 0.0f;

    const int tr = tid >> 4;   // row group 0..15  (rows tr + 16*i)
    const int tc = tid & 15;   // col group 0..15

    const int kb_max = causal ? ((q0 + BQ - 1) / BKV) : (S_LEN / BKV - 1);

    for (int kb = 0; kb <= kb_max; kb++) {
        const int k0 = kb * BKV;
        __syncthreads();  // protect Ss/Vs consumed by previous iteration (and Q on iter 0)

        // Load K,V blocks: 64x128 floats each = 2048 float4 (8 per thread each)
#pragma unroll
        for (int i = 0; i < 8; i++) {
            int f  = tid + i * 256;
            int r  = f >> 5;
            int c4 = (f & 31) << 2;
            size_t goff = (size_t)(k0 + r) * D_MODEL + h * HDIM + c4;
            float4 kv = *(const float4*)(g_k + goff);
            *(float4*)&Ks[r * QSTR + c4] = kv;
            float4 vv = *(const float4*)(g_v + goff);
            *(float4*)&Vs[r * VSTR + c4] = vv;
        }
        __syncthreads();

        // S = Q * K^T   (128x64 tile; 8x4 per thread, strided mapping)
        float s[8][4];
#pragma unroll
        for (int i = 0; i < 8; i++)
#pragma unroll
            for (int j = 0; j < 4; j++) s[i][j] = 0.0f;

#pragma unroll 2
        for (int d = 0; d < HDIM; d += 4) {
            float4 qf[8], kf[4];
#pragma unroll
            for (int i = 0; i < 8; i++)
                qf[i] = *(const float4*)&Qs[(tr + 16 * i) * QSTR + d];
#pragma unroll
            for (int j = 0; j < 4; j++)
                kf[j] = *(const float4*)&Ks[(tc + 16 * j) * QSTR + d];
#pragma unroll
            for (int i = 0; i < 8; i++)
#pragma unroll
                for (int j = 0; j < 4; j++) {
                    s[i][j] = fmaf(qf[i].x, kf[j].x, s[i][j]);
                    s[i][j] = fmaf(qf[i].y, kf[j].y, s[i][j]);
                    s[i][j] = fmaf(qf[i].z, kf[j].z, s[i][j]);
                    s[i][j] = fmaf(qf[i].w, kf[j].w, s[i][j]);
                }
        }

        const bool maybe_mask = causal && (k0 + BKV - 1 > q0);
#pragma unroll
        for (int i = 0; i < 8; i++) {
            int r = tr + 16 * i;
#pragma unroll
            for (int j = 0; j < 4; j++) {
                int c = tc + 16 * j;
                float val = s[i][j] * sm_scale;
                if (maybe_mask && (k0 + c > q0 + r)) val = -1e30f;
                Ss[r * SSTR + c] = val;
            }
        }
        __syncthreads();

        // Online softmax update (one thread per query row, float4-vectorized)
        if (tid < BQ) {
            float4* row = (float4*)&Ss[tid * SSTR];
            float mo = m_s[tid];
            float mx = mo;
#pragma unroll
            for (int ii = 0; ii < BKV / 4; ii++) {
                float4 t = row[ii];
                mx = fmaxf(mx, fmaxf(fmaxf(t.x, t.y), fmaxf(t.z, t.w)));
            }
            float a = __expf(mo - mx);
            float sum = 0.0f;
#pragma unroll
            for (int ii = 0; ii < BKV / 4; ii++) {
                float4 t = row[ii];
                t.x = __expf(t.x - mx); t.y = __expf(t.y - mx);
                t.z = __expf(t.z - mx); t.w = __expf(t.w - mx);
                row[ii] = t;
                sum += t.x + t.y + t.z + t.w;
            }
            m_s[tid]  = mx;
            al_s[tid] = a;
            l_s[tid]  = l_s[tid] * a + sum;
        }
        __syncthreads();

        // Rescale O and accumulate P*V (128x128; 8 rows x 8 cols per thread)
#pragma unroll
        for (int i = 0; i < 8; i++) {
            float a = al_s[tr + 16 * i];
#pragma unroll
            for (int j = 0; j < 8; j++) o[i][j] *= a;
        }
#pragma unroll 2
        for (int kk = 0; kk < BKV; kk++) {
            float4 va = *(const float4*)&Vs[kk * VSTR + tc * 4];
            float4 vb = *(const float4*)&Vs[kk * VSTR + 64 + tc * 4];
#pragma unroll
            for (int i = 0; i < 8; i++) {
                float p = Ss[(tr + 16 * i) * SSTR + kk];
                o[i][0] = fmaf(p, va.x, o[i][0]);
                o[i][1] = fmaf(p, va.y, o[i][1]);
                o[i][2] = fmaf(p, va.z, o[i][2]);
                o[i][3] = fmaf(p, va.w, o[i][3]);
                o[i][4] = fmaf(p, vb.x, o[i][4]);
                o[i][5] = fmaf(p, vb.y, o[i][5]);
                o[i][6] = fmaf(p, vb.z, o[i][6]);
                o[i][7] = fmaf(p, vb.w, o[i][7]);
            }
        }
    }

    // Epilogue: O /= l, write out
#pragma unroll
    for (int i = 0; i < 8; i++) {
        int r = tr + 16 * i;
        float inv = 1.0f / l_s[r];
        float4 v0 = make_float4(o[i][0] * inv, o[i][1] * inv, o[i][2] * inv, o[i][3] * inv);
        float4 v1 = make_float4(o[i][4] * inv, o[i][5] * inv, o[i][6] * inv, o[i][7] * inv);
        float* orow = g_o + (size_t)(q0 + r) * D_MODEL + h * HDIM;
        *(float4*)(orow + tc * 4)      = v0;
        *(float4*)(orow + 64 + tc * 4) = v1;
    }
}

// ---------------------------------------------------------------------------
// Launch
// ---------------------------------------------------------------------------
extern "C" void kernel_launch(void* const* d_in, const int* in_sizes, int n_in,
                              void* d_out, int out_size)
{
    const float* x  = (const float*)d_in[0];
    const float* wq = (const float*)d_in[1];
    const float* wk = (const float*)d_in[2];
    const float* wv = (const float*)d_in[3];
    const float* wo = (const float*)d_in[4];
    const int* causal = (const int*)d_in[5];
    float* out = (float*)d_out;

    float *q, *k, *v, *o;
    cudaGetSymbolAddress((void**)&q, g_q);
    cudaGetSymbolAddress((void**)&k, g_k);
    cudaGetSymbolAddress((void**)&v, g_v);
    cudaGetSymbolAddress((void**)&o, g_o);

    // QKV projections (fused as gridDim.z = 3)
    dim3 gqkv(D_MODEL / BN, S_LEN / BM, 3);
    gemm_nt_kernel<<<gqkv, 256>>>(x, wq, wk, wv, q, k, v, S_LEN, D_MODEL, D_MODEL);

    // Flash attention
    size_t smem_bytes = (size_t)(BQ * QSTR + BKV * QSTR + BKV * VSTR + BQ * SSTR + 3 * BQ) * sizeof(float);
    cudaFuncSetAttribute(attn_kernel, cudaFuncAttributeMaxDynamicSharedMemorySize, (int)smem_bytes);
    attn_kernel<<<dim3(S_LEN / BQ, NHEADS), 256, smem_bytes>>>(causal);

    // Output projection
    dim3 gout(D_MODEL / BN, S_LEN / BM, 1);
    gemm_nt_kernel<<<gout, 256>>>(o, wo, wo, wo, out, out, out, S_LEN, D_MODEL, D_MODEL);
}

// round 3
// speedup vs baseline: 1.4954x; 1.4954x over previous
#include <cuda_runtime.h>
#include <cuda_bf16.h>
#include <math.h>
#include <stdint.h>

#define S_LEN   4096
#define D_MODEL 2048
#define NHEADS  16
#define HDIM    128

// ---------------------------------------------------------------------------
// Scratch (device globals: allocation-guard-safe)
// ---------------------------------------------------------------------------
__device__ float g_q[S_LEN * D_MODEL];
__device__ float g_k[S_LEN * D_MODEL];
__device__ float g_v[S_LEN * D_MODEL];
__device__ float g_o[S_LEN * D_MODEL];

__device__ __nv_bfloat16 g_xhi[S_LEN * D_MODEL];
__device__ __nv_bfloat16 g_xlo[S_LEN * D_MODEL];
__device__ __nv_bfloat16 g_ohi[S_LEN * D_MODEL];
__device__ __nv_bfloat16 g_olo[S_LEN * D_MODEL];
__device__ __nv_bfloat16 g_wqhi[D_MODEL * D_MODEL];
__device__ __nv_bfloat16 g_wqlo[D_MODEL * D_MODEL];
__device__ __nv_bfloat16 g_wkhi[D_MODEL * D_MODEL];
__device__ __nv_bfloat16 g_wklo[D_MODEL * D_MODEL];
__device__ __nv_bfloat16 g_wvhi[D_MODEL * D_MODEL];
__device__ __nv_bfloat16 g_wvlo[D_MODEL * D_MODEL];
__device__ __nv_bfloat16 g_wohi[D_MODEL * D_MODEL];
__device__ __nv_bfloat16 g_wolo[D_MODEL * D_MODEL];

// ---------------------------------------------------------------------------
// Helpers
// ---------------------------------------------------------------------------
__device__ __forceinline__ uint32_t smem_u32(const void* p) {
    uint32_t a;
    asm("{ .reg .u64 t; cvta.to.shared.u64 t, %1; cvt.u32.u64 %0, t; }" : "=r"(a) : "l"(p));
    return a;
}

#define LDSM_X4(r0, r1, r2, r3, addr)                                         \
    asm volatile("ldmatrix.sync.aligned.m8n8.x4.shared.b16 {%0,%1,%2,%3}, [%4];" \
        : "=r"(r0), "=r"(r1), "=r"(r2), "=r"(r3) : "r"(addr))

__device__ __forceinline__ void mma_bf16(float& c0, float& c1, float& c2, float& c3,
                                         uint32_t a0, uint32_t a1, uint32_t a2, uint32_t a3,
                                         uint32_t b0, uint32_t b1) {
    asm volatile(
        "mma.sync.aligned.m16n8k16.row.col.f32.bf16.bf16.f32 "
        "{%0,%1,%2,%3}, {%4,%5,%6,%7}, {%8,%9}, {%0,%1,%2,%3};"
        : "+f"(c0), "+f"(c1), "+f"(c2), "+f"(c3)
        : "r"(a0), "r"(a1), "r"(a2), "r"(a3), "r"(b0), "r"(b1));
}

// ---------------------------------------------------------------------------
// fp32 -> bf16 hi/lo split
// ---------------------------------------------------------------------------
__global__ __launch_bounds__(256) void split_kernel(
    const float4* __restrict__ src, __nv_bfloat162* __restrict__ hi,
    __nv_bfloat162* __restrict__ lo, int n4)
{
    int i = blockIdx.x * blockDim.x + threadIdx.x;
    if (i >= n4) return;
    float4 v = src[i];
    __nv_bfloat16 hx = __float2bfloat16(v.x), hy = __float2bfloat16(v.y);
    __nv_bfloat16 hz = __float2bfloat16(v.z), hw = __float2bfloat16(v.w);
    float lx = v.x - __bfloat162float(hx), ly = v.y - __bfloat162float(hy);
    float lz = v.z - __bfloat162float(hz), lw = v.w - __bfloat162float(hw);
    hi[2 * i + 0] = __nv_bfloat162(hx, hy);
    hi[2 * i + 1] = __nv_bfloat162(hz, hw);
    lo[2 * i + 0] = __nv_bfloat162(__float2bfloat16(lx), __float2bfloat16(ly));
    lo[2 * i + 1] = __nv_bfloat162(__float2bfloat16(lz), __float2bfloat16(lw));
}

// ---------------------------------------------------------------------------
// bf16x3 GEMM via mma.sync (NT): C[m,n] = sum_k A[m,k]*B[n,k]
// CTA: 128x128 tile, 256 threads (8 warps = 2m x 4n), warp tile 64x32.
// Smem: Ahi/Alo/Bhi/Blo 128x64 bf16, SW128 swizzle, 64KB total.
// ---------------------------------------------------------------------------
#define GBK      64
#define GK_ITERS (D_MODEL / GBK)   // 32
#define T_AHI    0
#define T_ALO    16384
#define T_BHI    32768
#define T_BLO    49152
#define GEMM_SMEM 65536

__device__ __forceinline__ uint32_t swz(uint32_t off) {
    return off ^ ((off >> 3) & 0x70);
}

__device__ __forceinline__ void load_tile64(
    const __nv_bfloat16* __restrict__ src, char* dst, int row0, int k0, int tid)
{
#pragma unroll
    for (int i = 0; i < 4; i++) {
        int f = i * 256 + tid;
        int r = f >> 3;            // 0..127
        int c = f & 7;             // 16B chunk
        uint4 v = *(const uint4*)(src + (size_t)(row0 + r) * D_MODEL + k0 + c * 8);
        *(uint4*)(dst + swz((uint32_t)(r * 128 + c * 16))) = v;
    }
}

__global__ __launch_bounds__(256) void gemm_mma_kernel(
    const __nv_bfloat16* __restrict__ Ahi, const __nv_bfloat16* __restrict__ Alo,
    const __nv_bfloat16* __restrict__ Bhi0, const __nv_bfloat16* __restrict__ Blo0,
    const __nv_bfloat16* __restrict__ Bhi1, const __nv_bfloat16* __restrict__ Blo1,
    const __nv_bfloat16* __restrict__ Bhi2, const __nv_bfloat16* __restrict__ Blo2,
    float* __restrict__ C0, float* __restrict__ C1, float* __restrict__ C2)
{
    extern __shared__ char smem[];
    const uint32_t sbase = smem_u32(smem);
    const int tid  = threadIdx.x;
    const int wid  = tid >> 5;
    const int lane = tid & 31;

    const __nv_bfloat16* Bhi = (blockIdx.z == 0) ? Bhi0 : (blockIdx.z == 1) ? Bhi1 : Bhi2;
    const __nv_bfloat16* Blo = (blockIdx.z == 0) ? Blo0 : (blockIdx.z == 1) ? Blo1 : Blo2;
    float*               C   = (blockIdx.z == 0) ? C0   : (blockIdx.z == 1) ? C1   : C2;

    const int m0 = blockIdx.y * 128;
    const int n0 = blockIdx.x * 128;

    const int warp_m = wid & 1;        // 0..1 -> 64-row half
    const int warp_n = wid >> 1;       // 0..3 -> 32-col quarter

    // Per-lane ldmatrix row-part offsets (bytes, pre-swizzle)
    // A: per m-tile mt: row = warp_m*64 + mt*16 + (lane&15), chunk = (lane>>4)*16
    const uint32_t a_rowpart = (uint32_t)((warp_m * 64 + (lane & 15)) * 128 + (lane >> 4) * 16);
    // B: per n-pair np: row = warp_n*32 + np*16 + (lane&7) + ((lane>>4)*8), half = ((lane>>3)&1)*16
    const uint32_t b_rowpart = (uint32_t)((warp_n * 32 + (lane & 7) + ((lane >> 4) << 3)) * 128
                                          + ((lane >> 3) & 1) * 16);

    float acc[4][4][4];
#pragma unroll
    for (int i = 0; i < 4; i++)
#pragma unroll
        for (int j = 0; j < 4; j++)
#pragma unroll
            for (int t = 0; t < 4; t++) acc[i][j][t] = 0.0f;

    for (int it = 0; it < GK_ITERS; it++) {
        const int k0 = it * GBK;
        __syncthreads();
        load_tile64(Ahi, smem + T_AHI, m0, k0, tid);
        load_tile64(Alo, smem + T_ALO, m0, k0, tid);
        load_tile64(Bhi, smem + T_BHI, n0, k0, tid);
        load_tile64(Blo, smem + T_BLO, n0, k0, tid);
        __syncthreads();

#pragma unroll
        for (int ks = 0; ks < 4; ks++) {
            const uint32_t kbyte = (uint32_t)(ks * 32);

            // B fragments: 4 n-tiles x 2 regs, hi and lo
            uint32_t bh[8], bl[8];
            {
                uint32_t ad0 = sbase + T_BHI + swz(b_rowpart + kbyte);
                uint32_t ad1 = sbase + T_BHI + swz(b_rowpart + 16 * 128 + kbyte);
                LDSM_X4(bh[0], bh[1], bh[2], bh[3], ad0);
                LDSM_X4(bh[4], bh[5], bh[6], bh[7], ad1);
                uint32_t ad2 = sbase + T_BLO + swz(b_rowpart + kbyte);
                uint32_t ad3 = sbase + T_BLO + swz(b_rowpart + 16 * 128 + kbyte);
                LDSM_X4(bl[0], bl[1], bl[2], bl[3], ad2);
                LDSM_X4(bl[4], bl[5], bl[6], bl[7], ad3);
            }

            // A hi fragments: 4 m-tiles x 4 regs
            uint32_t af[16];
#pragma unroll
            for (int mt = 0; mt < 4; mt++) {
                uint32_t ad = sbase + T_AHI + swz(a_rowpart + (uint32_t)(mt * 16 * 128) + kbyte);
                LDSM_X4(af[mt * 4 + 0], af[mt * 4 + 1], af[mt * 4 + 2], af[mt * 4 + 3], ad);
            }
            // hi*hi and hi*lo
#pragma unroll
            for (int mt = 0; mt < 4; mt++)
#pragma unroll
                for (int nt = 0; nt < 4; nt++) {
                    mma_bf16(acc[mt][nt][0], acc[mt][nt][1], acc[mt][nt][2], acc[mt][nt][3],
                             af[mt*4+0], af[mt*4+1], af[mt*4+2], af[mt*4+3],
                             bh[nt*2+0], bh[nt*2+1]);
                    mma_bf16(acc[mt][nt][0], acc[mt][nt][1], acc[mt][nt][2], acc[mt][nt][3],
                             af[mt*4+0], af[mt*4+1], af[mt*4+2], af[mt*4+3],
                             bl[nt*2+0], bl[nt*2+1]);
                }

            // A lo fragments (reuse regs)
#pragma unroll
            for (int mt = 0; mt < 4; mt++) {
                uint32_t ad = sbase + T_ALO + swz(a_rowpart + (uint32_t)(mt * 16 * 128) + kbyte);
                LDSM_X4(af[mt * 4 + 0], af[mt * 4 + 1], af[mt * 4 + 2], af[mt * 4 + 3], ad);
            }
            // lo*hi
#pragma unroll
            for (int mt = 0; mt < 4; mt++)
#pragma unroll
                for (int nt = 0; nt < 4; nt++)
                    mma_bf16(acc[mt][nt][0], acc[mt][nt][1], acc[mt][nt][2], acc[mt][nt][3],
                             af[mt*4+0], af[mt*4+1], af[mt*4+2], af[mt*4+3],
                             bh[nt*2+0], bh[nt*2+1]);
        }
    }

    // Epilogue: write accumulators
#pragma unroll
    for (int mt = 0; mt < 4; mt++) {
        int row = m0 + warp_m * 64 + mt * 16 + (lane >> 2);
#pragma unroll
        for (int nt = 0; nt < 4; nt++) {
            int col = n0 + warp_n * 32 + nt * 8 + (lane & 3) * 2;
            *(float2*)(C + (size_t)row * D_MODEL + col) =
                make_float2(acc[mt][nt][0], acc[mt][nt][1]);
            *(float2*)(C + (size_t)(row + 8) * D_MODEL + col) =
                make_float2(acc[mt][nt][2], acc[mt][nt][3]);
        }
    }
}

// ---------------------------------------------------------------------------
// Flash attention, fp32, causal (unchanged)
// ---------------------------------------------------------------------------
#define BQ   128
#define BKV  64
#define QSTR 132
#define VSTR 128
#define SSTR 68

__global__ __launch_bounds__(256) void attn_kernel(const int* __restrict__ causal_flag)
{
    extern __shared__ float smf[];
    float* Qs   = smf;
    float* Ks   = Qs  + BQ * QSTR;
    float* Vs   = Ks  + BKV * QSTR;
    float* Ss   = Vs  + BKV * VSTR;
    float* m_s  = Ss  + BQ * SSTR;
    float* l_s  = m_s + BQ;
    float* al_s = l_s + BQ;

    const int tid = threadIdx.x;
    const int qb  = blockIdx.x;
    const int h   = blockIdx.y;
    const int q0  = qb * BQ;
    const int causal = *causal_flag;
    const float sm_scale = 0.08838834764831845f;

#pragma unroll
    for (int i = 0; i < 16; i++) {
        int f  = tid + i * 256;
        int r  = f >> 5;
        int c4 = (f & 31) << 2;
        float4 v = *(const float4*)(g_q + (size_t)(q0 + r) * D_MODEL + h * HDIM + c4);
        *(float4*)&Qs[r * QSTR + c4] = v;
    }
    if (tid < BQ) { m_s[tid] = -1e30f; l_s[tid] = 0.0f; }

    float o[8][8];
#pragma unroll
    for (int i = 0; i < 8; i++)
#pragma unroll
        for (int j = 0; j < 8; j++) o[i][j] = 0.0f;

    const int tr = tid >> 4;
    const int tc = tid & 15;
    const int kb_max = causal ? ((q0 + BQ - 1) / BKV) : (S_LEN / BKV - 1);

    for (int kb = 0; kb <= kb_max; kb++) {
        const int k0 = kb * BKV;
        __syncthreads();

#pragma unroll
        for (int i = 0; i < 8; i++) {
            int f  = tid + i * 256;
            int r  = f >> 5;
            int c4 = (f & 31) << 2;
            size_t goff = (size_t)(k0 + r) * D_MODEL + h * HDIM + c4;
            float4 kv = *(const float4*)(g_k + goff);
            *(float4*)&Ks[r * QSTR + c4] = kv;
            float4 vv = *(const float4*)(g_v + goff);
            *(float4*)&Vs[r * VSTR + c4] = vv;
        }
        __syncthreads();

        float s[8][4];
#pragma unroll
        for (int i = 0; i < 8; i++)
#pragma unroll
            for (int j = 0; j < 4; j++) s[i][j] = 0.0f;

#pragma unroll 2
        for (int d = 0; d < HDIM; d += 4) {
            float4 qf[8], kf[4];
#pragma unroll
            for (int i = 0; i < 8; i++)
                qf[i] = *(const float4*)&Qs[(tr + 16 * i) * QSTR + d];
#pragma unroll
            for (int j = 0; j < 4; j++)
                kf[j] = *(const float4*)&Ks[(tc + 16 * j) * QSTR + d];
#pragma unroll
            for (int i = 0; i < 8; i++)
#pragma unroll
                for (int j = 0; j < 4; j++) {
                    s[i][j] = fmaf(qf[i].x, kf[j].x, s[i][j]);
                    s[i][j] = fmaf(qf[i].y, kf[j].y, s[i][j]);
                    s[i][j] = fmaf(qf[i].z, kf[j].z, s[i][j]);
                    s[i][j] = fmaf(qf[i].w, kf[j].w, s[i][j]);
                }
        }

        const bool maybe_mask = causal && (k0 + BKV - 1 > q0);
#pragma unroll
        for (int i = 0; i < 8; i++) {
            int r = tr + 16 * i;
#pragma unroll
            for (int j = 0; j < 4; j++) {
                int c = tc + 16 * j;
                float val = s[i][j] * sm_scale;
                if (maybe_mask && (k0 + c > q0 + r)) val = -1e30f;
                Ss[r * SSTR + c] = val;
            }
        }
        __syncthreads();

        if (tid < BQ) {
            float4* row = (float4*)&Ss[tid * SSTR];
            float mo = m_s[tid];
            float mx = mo;
#pragma unroll
            for (int ii = 0; ii < BKV / 4; ii++) {
                float4 t = row[ii];
                mx = fmaxf(mx, fmaxf(fmaxf(t.x, t.y), fmaxf(t.z, t.w)));
            }
            float a = __expf(mo - mx);
            float sum = 0.0f;
#pragma unroll
            for (int ii = 0; ii < BKV / 4; ii++) {
                float4 t = row[ii];
                t.x = __expf(t.x - mx); t.y = __expf(t.y - mx);
                t.z = __expf(t.z - mx); t.w = __expf(t.w - mx);
                row[ii] = t;
                sum += t.x + t.y + t.z + t.w;
            }
            m_s[tid]  = mx;
            al_s[tid] = a;
            l_s[tid]  = l_s[tid] * a + sum;
        }
        __syncthreads();

#pragma unroll
        for (int i = 0; i < 8; i++) {
            float a = al_s[tr + 16 * i];
#pragma unroll
            for (int j = 0; j < 8; j++) o[i][j] *= a;
        }
#pragma unroll 2
        for (int kk = 0; kk < BKV; kk++) {
            float4 va = *(const float4*)&Vs[kk * VSTR + tc * 4];
            float4 vb = *(const float4*)&Vs[kk * VSTR + 64 + tc * 4];
#pragma unroll
            for (int i = 0; i < 8; i++) {
                float p = Ss[(tr + 16 * i) * SSTR + kk];
                o[i][0] = fmaf(p, va.x, o[i][0]);
                o[i][1] = fmaf(p, va.y, o[i][1]);
                o[i][2] = fmaf(p, va.z, o[i][2]);
                o[i][3] = fmaf(p, va.w, o[i][3]);
                o[i][4] = fmaf(p, vb.x, o[i][4]);
                o[i][5] = fmaf(p, vb.y, o[i][5]);
                o[i][6] = fmaf(p, vb.z, o[i][6]);
                o[i][7] = fmaf(p, vb.w, o[i][7]);
            }
        }
    }

#pragma unroll
    for (int i = 0; i < 8; i++) {
        int r = tr + 16 * i;
        float inv = 1.0f / l_s[r];
        float4 v0 = make_float4(o[i][0] * inv, o[i][1] * inv, o[i][2] * inv, o[i][3] * inv);
        float4 v1 = make_float4(o[i][4] * inv, o[i][5] * inv, o[i][6] * inv, o[i][7] * inv);
        float* orow = g_o + (size_t)(q0 + r) * D_MODEL + h * HDIM;
        *(float4*)(orow + tc * 4)      = v0;
        *(float4*)(orow + 64 + tc * 4) = v1;
    }
}

// ---------------------------------------------------------------------------
// Launch
// ---------------------------------------------------------------------------
extern "C" void kernel_launch(void* const* d_in, const int* in_sizes, int n_in,
                              void* d_out, int out_size)
{
    const float* x  = (const float*)d_in[0];
    const float* wq = (const float*)d_in[1];
    const float* wk = (const float*)d_in[2];
    const float* wv = (const float*)d_in[3];
    const float* wo = (const float*)d_in[4];
    const int* causal = (const int*)d_in[5];
    float* out = (float*)d_out;

    float *q, *k, *v, *o;
    cudaGetSymbolAddress((void**)&q, g_q);
    cudaGetSymbolAddress((void**)&k, g_k);
    cudaGetSymbolAddress((void**)&v, g_v);
    cudaGetSymbolAddress((void**)&o, g_o);
    __nv_bfloat16 *xhi, *xlo, *ohi, *olo, *wqh, *wql, *wkh, *wkl, *wvh, *wvl, *woh, *wol;
    cudaGetSymbolAddress((void**)&xhi, g_xhi);  cudaGetSymbolAddress((void**)&xlo, g_xlo);
    cudaGetSymbolAddress((void**)&ohi, g_ohi);  cudaGetSymbolAddress((void**)&olo, g_olo);
    cudaGetSymbolAddress((void**)&wqh, g_wqhi); cudaGetSymbolAddress((void**)&wql, g_wqlo);
    cudaGetSymbolAddress((void**)&wkh, g_wkhi); cudaGetSymbolAddress((void**)&wkl, g_wklo);
    cudaGetSymbolAddress((void**)&wvh, g_wvhi); cudaGetSymbolAddress((void**)&wvl, g_wvlo);
    cudaGetSymbolAddress((void**)&woh, g_wohi); cudaGetSymbolAddress((void**)&wol, g_wolo);

    const int nx4 = S_LEN * D_MODEL / 4;
    const int nw4 = D_MODEL * D_MODEL / 4;

    split_kernel<<<nx4 / 256, 256>>>((const float4*)x,  (__nv_bfloat162*)xhi, (__nv_bfloat162*)xlo, nx4);
    split_kernel<<<nw4 / 256, 256>>>((const float4*)wq, (__nv_bfloat162*)wqh, (__nv_bfloat162*)wql, nw4);
    split_kernel<<<nw4 / 256, 256>>>((const float4*)wk, (__nv_bfloat162*)wkh, (__nv_bfloat162*)wkl, nw4);
    split_kernel<<<nw4 / 256, 256>>>((const float4*)wv, (__nv_bfloat162*)wvh, (__nv_bfloat162*)wvl, nw4);
    split_kernel<<<nw4 / 256, 256>>>((const float4*)wo, (__nv_bfloat162*)woh, (__nv_bfloat162*)wol, nw4);

    cudaFuncSetAttribute(gemm_mma_kernel, cudaFuncAttributeMaxDynamicSharedMemorySize, GEMM_SMEM);
    dim3 gqkv(D_MODEL / 128, S_LEN / 128, 3);
    gemm_mma_kernel<<<gqkv, 256, GEMM_SMEM>>>(xhi, xlo, wqh, wql, wkh, wkl, wvh, wvl, q, k, v);

    size_t smem_bytes = (size_t)(BQ * QSTR + BKV * QSTR + BKV * VSTR + BQ * SSTR + 3 * BQ) * sizeof(float);
    cudaFuncSetAttribute(attn_kernel, cudaFuncAttributeMaxDynamicSharedMemorySize, (int)smem_bytes);
    attn_kernel<<<dim3(S_LEN / BQ, NHEADS), 256, smem_bytes>>>(causal);

    split_kernel<<<nx4 / 256, 256>>>((const float4*)o, (__nv_bfloat162*)ohi, (__nv_bfloat162*)olo, nx4);
    dim3 gout(D_MODEL / 128, S_LEN / 128, 1);
    gemm_mma_kernel<<<gout, 256, GEMM_SMEM>>>(ohi, olo, woh, wol, woh, wol, woh, wol, out, out, out);
}

// round 4
// speedup vs baseline: 2.3942x; 1.6011x over previous
#include <cuda_runtime.h>
#include <cuda_bf16.h>
#include <math.h>
#include <stdint.h>

#define S_LEN   4096
#define D_MODEL 2048
#define NHEADS  16
#define HDIM    128

// ---------------------------------------------------------------------------
// Scratch (device globals: allocation-guard-safe)
// ---------------------------------------------------------------------------
__device__ __nv_bfloat16 g_xhi[S_LEN * D_MODEL];
__device__ __nv_bfloat16 g_xlo[S_LEN * D_MODEL];
__device__ __nv_bfloat16 g_qhi[S_LEN * D_MODEL];
__device__ __nv_bfloat16 g_qlo[S_LEN * D_MODEL];
__device__ __nv_bfloat16 g_khi[S_LEN * D_MODEL];
__device__ __nv_bfloat16 g_klo[S_LEN * D_MODEL];
__device__ __nv_bfloat16 g_vhi[S_LEN * D_MODEL];
__device__ __nv_bfloat16 g_vlo[S_LEN * D_MODEL];
__device__ __nv_bfloat16 g_ohi[S_LEN * D_MODEL];
__device__ __nv_bfloat16 g_olo[S_LEN * D_MODEL];
__device__ __nv_bfloat16 g_wqhi[D_MODEL * D_MODEL];
__device__ __nv_bfloat16 g_wqlo[D_MODEL * D_MODEL];
__device__ __nv_bfloat16 g_wkhi[D_MODEL * D_MODEL];
__device__ __nv_bfloat16 g_wklo[D_MODEL * D_MODEL];
__device__ __nv_bfloat16 g_wvhi[D_MODEL * D_MODEL];
__device__ __nv_bfloat16 g_wvlo[D_MODEL * D_MODEL];
__device__ __nv_bfloat16 g_wohi[D_MODEL * D_MODEL];
__device__ __nv_bfloat16 g_wolo[D_MODEL * D_MODEL];

// ---------------------------------------------------------------------------
// Helpers
// ---------------------------------------------------------------------------
__device__ __forceinline__ uint32_t smem_u32(const void* p) {
    uint32_t a;
    asm("{ .reg .u64 t; cvta.to.shared.u64 t, %1; cvt.u32.u64 %0, t; }" : "=r"(a) : "l"(p));
    return a;
}

#define LDSM_X4(r0, r1, r2, r3, addr)                                         \
    asm volatile("ldmatrix.sync.aligned.m8n8.x4.shared.b16 {%0,%1,%2,%3}, [%4];" \
        : "=r"(r0), "=r"(r1), "=r"(r2), "=r"(r3) : "r"(addr))

#define LDSM_X4_T(r0, r1, r2, r3, addr)                                       \
    asm volatile("ldmatrix.sync.aligned.m8n8.x4.trans.shared.b16 {%0,%1,%2,%3}, [%4];" \
        : "=r"(r0), "=r"(r1), "=r"(r2), "=r"(r3) : "r"(addr))

__device__ __forceinline__ void mma_bf16(float& c0, float& c1, float& c2, float& c3,
                                         uint32_t a0, uint32_t a1, uint32_t a2, uint32_t a3,
                                         uint32_t b0, uint32_t b1) {
    asm volatile(
        "mma.sync.aligned.m16n8k16.row.col.f32.bf16.bf16.f32 "
        "{%0,%1,%2,%3}, {%4,%5,%6,%7}, {%8,%9}, {%0,%1,%2,%3};"
        : "+f"(c0), "+f"(c1), "+f"(c2), "+f"(c3)
        : "r"(a0), "r"(a1), "r"(a2), "r"(a3), "r"(b0), "r"(b1));
}

__device__ __forceinline__ uint32_t pack2(__nv_bfloat16 a, __nv_bfloat16 b) {
    __nv_bfloat162 t(a, b);
    return *reinterpret_cast<uint32_t*>(&t);
}

// Split (x, y) fp32 pair into bf16x2 hi and lo words (lo = residual)
__device__ __forceinline__ void pack_hilo(float x, float y, uint32_t& hi, uint32_t& lo) {
    __nv_bfloat16 hx = __float2bfloat16(x), hy = __float2bfloat16(y);
    float rx = x - __bfloat162float(hx), ry = y - __bfloat162float(hy);
    hi = pack2(hx, hy);
    lo = pack2(__float2bfloat16(rx), __float2bfloat16(ry));
}

// Swizzle for 128-byte-row tiles (GEMM)
__device__ __forceinline__ uint32_t swz(uint32_t off)  { return off ^ ((off >> 3) & 0x70); }
// Swizzle for 256-byte-row tiles (attention)
__device__ __forceinline__ uint32_t vswz(uint32_t off) { return off ^ ((off >> 4) & 0x70); }

// ---------------------------------------------------------------------------
// fp32 -> bf16 hi/lo split (for x and weights)
// ---------------------------------------------------------------------------
__global__ __launch_bounds__(256) void split_kernel(
    const float4* __restrict__ src, __nv_bfloat162* __restrict__ hi,
    __nv_bfloat162* __restrict__ lo, int n4)
{
    int i = blockIdx.x * blockDim.x + threadIdx.x;
    if (i >= n4) return;
    float4 v = src[i];
    uint32_t h0, l0, h1, l1;
    pack_hilo(v.x, v.y, h0, l0);
    pack_hilo(v.z, v.w, h1, l1);
    *reinterpret_cast<uint32_t*>(&hi[2 * i + 0]) = h0;
    *reinterpret_cast<uint32_t*>(&hi[2 * i + 1]) = h1;
    *reinterpret_cast<uint32_t*>(&lo[2 * i + 0]) = l0;
    *reinterpret_cast<uint32_t*>(&lo[2 * i + 1]) = l1;
}

// ---------------------------------------------------------------------------
// bf16x3 GEMM via mma.sync (NT). BF16OUT: epilogue writes bf16 hi/lo pair
// arrays instead of fp32 C.
// ---------------------------------------------------------------------------
#define GBK      64
#define GK_ITERS (D_MODEL / GBK)
#define T_AHI    0
#define T_ALO    16384
#define T_BHI    32768
#define T_BLO    49152
#define GEMM_SMEM 65536

__device__ __forceinline__ void load_tile64(
    const __nv_bfloat16* __restrict__ src, char* dst, int row0, int k0, int tid)
{
#pragma unroll
    for (int i = 0; i < 4; i++) {
        int f = i * 256 + tid;
        int r = f >> 3;
        int c = f & 7;
        uint4 v = *(const uint4*)(src + (size_t)(row0 + r) * D_MODEL + k0 + c * 8);
        *(uint4*)(dst + swz((uint32_t)(r * 128 + c * 16))) = v;
    }
}

template<bool BF16OUT>
__global__ __launch_bounds__(256) void gemm_mma_kernel(
    const __nv_bfloat16* __restrict__ Ahi, const __nv_bfloat16* __restrict__ Alo,
    const __nv_bfloat16* __restrict__ Bhi0, const __nv_bfloat16* __restrict__ Blo0,
    const __nv_bfloat16* __restrict__ Bhi1, const __nv_bfloat16* __restrict__ Blo1,
    const __nv_bfloat16* __restrict__ Bhi2, const __nv_bfloat16* __restrict__ Blo2,
    float* __restrict__ C0,
    __nv_bfloat16* __restrict__ Chi0, __nv_bfloat16* __restrict__ Clo0,
    __nv_bfloat16* __restrict__ Chi1, __nv_bfloat16* __restrict__ Clo1,
    __nv_bfloat16* __restrict__ Chi2, __nv_bfloat16* __restrict__ Clo2)
{
    extern __shared__ char smem[];
    const uint32_t sbase = smem_u32(smem);
    const int tid  = threadIdx.x;
    const int wid  = tid >> 5;
    const int lane = tid & 31;

    const __nv_bfloat16* Bhi = (blockIdx.z == 0) ? Bhi0 : (blockIdx.z == 1) ? Bhi1 : Bhi2;
    const __nv_bfloat16* Blo = (blockIdx.z == 0) ? Blo0 : (blockIdx.z == 1) ? Blo1 : Blo2;
    __nv_bfloat16* Chi = (blockIdx.z == 0) ? Chi0 : (blockIdx.z == 1) ? Chi1 : Chi2;
    __nv_bfloat16* Clo = (blockIdx.z == 0) ? Clo0 : (blockIdx.z == 1) ? Clo1 : Clo2;

    const int m0 = blockIdx.y * 128;
    const int n0 = blockIdx.x * 128;

    const int warp_m = wid & 1;
    const int warp_n = wid >> 1;

    const uint32_t a_rowpart = (uint32_t)((warp_m * 64 + (lane & 15)) * 128 + (lane >> 4) * 16);
    const uint32_t b_rowpart = (uint32_t)((warp_n * 32 + (lane & 7) + ((lane >> 4) << 3)) * 128
                                          + ((lane >> 3) & 1) * 16);

    float acc[4][4][4];
#pragma unroll
    for (int i = 0; i < 4; i++)
#pragma unroll
        for (int j = 0; j < 4; j++)
#pragma unroll
            for (int t = 0; t < 4; t++) acc[i][j][t] = 0.0f;

    for (int it = 0; it < GK_ITERS; it++) {
        const int k0 = it * GBK;
        __syncthreads();
        load_tile64(Ahi, smem + T_AHI, m0, k0, tid);
        load_tile64(Alo, smem + T_ALO, m0, k0, tid);
        load_tile64(Bhi, smem + T_BHI, n0, k0, tid);
        load_tile64(Blo, smem + T_BLO, n0, k0, tid);
        __syncthreads();

#pragma unroll
        for (int ks = 0; ks < 4; ks++) {
            const uint32_t kbyte = (uint32_t)(ks * 32);

            uint32_t bh[8], bl[8];
            {
                uint32_t ad0 = sbase + T_BHI + swz(b_rowpart + kbyte);
                uint32_t ad1 = sbase + T_BHI + swz(b_rowpart + 16 * 128 + kbyte);
                LDSM_X4(bh[0], bh[1], bh[2], bh[3], ad0);
                LDSM_X4(bh[4], bh[5], bh[6], bh[7], ad1);
                uint32_t ad2 = sbase + T_BLO + swz(b_rowpart + kbyte);
                uint32_t ad3 = sbase + T_BLO + swz(b_rowpart + 16 * 128 + kbyte);
                LDSM_X4(bl[0], bl[1], bl[2], bl[3], ad2);
                LDSM_X4(bl[4], bl[5], bl[6], bl[7], ad3);
            }

            uint32_t af[16];
#pragma unroll
            for (int mt = 0; mt < 4; mt++) {
                uint32_t ad = sbase + T_AHI + swz(a_rowpart + (uint32_t)(mt * 16 * 128) + kbyte);
                LDSM_X4(af[mt * 4 + 0], af[mt * 4 + 1], af[mt * 4 + 2], af[mt * 4 + 3], ad);
            }
#pragma unroll
            for (int mt = 0; mt < 4; mt++)
#pragma unroll
                for (int nt = 0; nt < 4; nt++) {
                    mma_bf16(acc[mt][nt][0], acc[mt][nt][1], acc[mt][nt][2], acc[mt][nt][3],
                             af[mt*4+0], af[mt*4+1], af[mt*4+2], af[mt*4+3],
                             bh[nt*2+0], bh[nt*2+1]);
                    mma_bf16(acc[mt][nt][0], acc[mt][nt][1], acc[mt][nt][2], acc[mt][nt][3],
                             af[mt*4+0], af[mt*4+1], af[mt*4+2], af[mt*4+3],
                             bl[nt*2+0], bl[nt*2+1]);
                }

#pragma unroll
            for (int mt = 0; mt < 4; mt++) {
                uint32_t ad = sbase + T_ALO + swz(a_rowpart + (uint32_t)(mt * 16 * 128) + kbyte);
                LDSM_X4(af[mt * 4 + 0], af[mt * 4 + 1], af[mt * 4 + 2], af[mt * 4 + 3], ad);
            }
#pragma unroll
            for (int mt = 0; mt < 4; mt++)
#pragma unroll
                for (int nt = 0; nt < 4; nt++)
                    mma_bf16(acc[mt][nt][0], acc[mt][nt][1], acc[mt][nt][2], acc[mt][nt][3],
                             af[mt*4+0], af[mt*4+1], af[mt*4+2], af[mt*4+3],
                             bh[nt*2+0], bh[nt*2+1]);
        }
    }

#pragma unroll
    for (int mt = 0; mt < 4; mt++) {
        int row = m0 + warp_m * 64 + mt * 16 + (lane >> 2);
#pragma unroll
        for (int nt = 0; nt < 4; nt++) {
            int col = n0 + warp_n * 32 + nt * 8 + (lane & 3) * 2;
            if (BF16OUT) {
                uint32_t h01, l01, h23, l23;
                pack_hilo(acc[mt][nt][0], acc[mt][nt][1], h01, l01);
                pack_hilo(acc[mt][nt][2], acc[mt][nt][3], h23, l23);
                *(uint32_t*)(Chi + (size_t)row * D_MODEL + col)       = h01;
                *(uint32_t*)(Clo + (size_t)row * D_MODEL + col)       = l01;
                *(uint32_t*)(Chi + (size_t)(row + 8) * D_MODEL + col) = h23;
                *(uint32_t*)(Clo + (size_t)(row + 8) * D_MODEL + col) = l23;
            } else {
                *(float2*)(C0 + (size_t)row * D_MODEL + col) =
                    make_float2(acc[mt][nt][0], acc[mt][nt][1]);
                *(float2*)(C0 + (size_t)(row + 8) * D_MODEL + col) =
                    make_float2(acc[mt][nt][2], acc[mt][nt][3]);
            }
        }
    }
}

// ---------------------------------------------------------------------------
// Flash attention on mma.sync, bf16x3 emulated fp32, causal.
// CTA: 128 q rows x 1 head, 8 warps. Warp w owns q rows {w*8..w*8+7} and
// {64+w*8..64+w*8+7} (interleaved for causal balance). BKV = 64 per iter.
// Smem: Q hi/lo persistent (64KB) + K/V hi/lo per iter (64KB) = 128KB.
// ---------------------------------------------------------------------------
#define ATT_QHI 0
#define ATT_QLO 32768
#define ATT_KHI 65536
#define ATT_KLO 81920
#define ATT_VHI 98304
#define ATT_VLO 114688
#define ATT_SMEM 131072

__global__ __launch_bounds__(256, 1) void attn_mma_kernel(const int* __restrict__ causal_flag)
{
    extern __shared__ char smem[];
    const uint32_t sb = smem_u32(smem);
    const int tid  = threadIdx.x;
    const int w    = tid >> 5;
    const int lane = tid & 31;
    const int q0   = blockIdx.x * 128;
    const int h    = blockIdx.y;
    const int causal = *causal_flag;
    const float sm_scale = 0.08838834764831845f;   // 1/sqrt(128)

    // ---- Q hi/lo -> smem (persistent) ----
#pragma unroll
    for (int t = 0; t < 2; t++) {
        const __nv_bfloat16* src = t ? g_qlo : g_qhi;
        const uint32_t dst = t ? ATT_QLO : ATT_QHI;
#pragma unroll
        for (int i = 0; i < 8; i++) {
            int f = i * 256 + tid;
            int row = f >> 4, ch = f & 15;
            uint4 v = *(const uint4*)(src + (size_t)(q0 + row) * D_MODEL + h * HDIM + ch * 8);
            *(uint4*)(smem + dst + vswz((uint32_t)(row * 256 + ch * 16))) = v;
        }
    }

    // Per-thread fragment geometry
    const int rq  = lane >> 2;              // 0..7
    const int cb  = (lane & 3) * 2;         // 0,2,4,6
    const int rg0 = q0 + w * 8 + rq;        // global q row for c0/c1
    const int rg1 = rg0 + 64;               // global q row for c2/c3

    // A-frag (Q) ldmatrix lane mapping
    const uint32_t a_row = (uint32_t)((((lane >> 3) & 1) ? 64 + w * 8 : w * 8) + (lane & 7));
    const uint32_t a_xr  = (a_row & 7) << 4;
    const uint32_t a_cb  = ((lane >> 4) & 1) * 16;
    // B-frag (K) lane mapping
    const uint32_t k_rbase = ((lane >> 4) & 1) * 8 + (lane & 7);
    const uint32_t k_cb    = ((lane >> 3) & 1) * 16;
    // B-frag (V, trans) lane mapping
    const uint32_t v_rbase = ((lane >> 3) & 1) * 8 + (lane & 7);
    const uint32_t v_cb    = ((lane >> 4) & 1) * 16;

    float o[16][4];
#pragma unroll
    for (int i = 0; i < 16; i++)
#pragma unroll
        for (int t = 0; t < 4; t++) o[i][t] = 0.0f;
    float m0v = -1e30f, m1v = -1e30f, l0 = 0.0f, l1 = 0.0f;

    const int kb_max = causal ? (q0 + 127) / 64 : (S_LEN / 64 - 1);

    for (int kb = 0; kb <= kb_max; kb++) {
        const int k0 = kb * 64;
        __syncthreads();
        // ---- K/V hi/lo tiles -> smem ----
#pragma unroll
        for (int t = 0; t < 4; t++) {
            const __nv_bfloat16* src = (t == 0) ? g_khi : (t == 1) ? g_klo : (t == 2) ? g_vhi : g_vlo;
            const uint32_t dst = (t == 0) ? ATT_KHI : (t == 1) ? ATT_KLO : (t == 2) ? ATT_VHI : ATT_VLO;
#pragma unroll
            for (int i = 0; i < 4; i++) {
                int f = i * 256 + tid;
                int row = f >> 4, ch = f & 15;
                uint4 v = *(const uint4*)(src + (size_t)(k0 + row) * D_MODEL + h * HDIM + ch * 8);
                *(uint4*)(smem + dst + vswz((uint32_t)(row * 256 + ch * 16))) = v;
            }
        }
        __syncthreads();

        // ---- S = Q K^T (bf16x3) ----
        float s[8][4];
#pragma unroll
        for (int i = 0; i < 8; i++)
#pragma unroll
            for (int t = 0; t < 4; t++) s[i][t] = 0.0f;

#pragma unroll
        for (int ks = 0; ks < 8; ks++) {
            const uint32_t aoff = a_row * 256 + (((uint32_t)(ks * 32) + a_cb) ^ a_xr);
            uint32_t ah0, ah1, ah2, ah3, al0, al1, al2, al3;
            LDSM_X4(ah0, ah1, ah2, ah3, sb + ATT_QHI + aoff);
            LDSM_X4(al0, al1, al2, al3, sb + ATT_QLO + aoff);
#pragma unroll
            for (int ng = 0; ng < 4; ng++) {
                const uint32_t krow = (uint32_t)(ng * 16) + k_rbase;
                const uint32_t koff = krow * 256 + (((uint32_t)(ks * 32) + k_cb) ^ ((krow & 7) << 4));
                uint32_t bh0, bh1, bh2, bh3, bl0, bl1, bl2, bl3;
                LDSM_X4(bh0, bh1, bh2, bh3, sb + ATT_KHI + koff);
                LDSM_X4(bl0, bl1, bl2, bl3, sb + ATT_KLO + koff);
                mma_bf16(s[2*ng][0], s[2*ng][1], s[2*ng][2], s[2*ng][3],
                         ah0, ah1, ah2, ah3, bh0, bh1);
                mma_bf16(s[2*ng][0], s[2*ng][1], s[2*ng][2], s[2*ng][3],
                         ah0, ah1, ah2, ah3, bl0, bl1);
                mma_bf16(s[2*ng][0], s[2*ng][1], s[2*ng][2], s[2*ng][3],
                         al0, al1, al2, al3, bh0, bh1);
                mma_bf16(s[2*ng+1][0], s[2*ng+1][1], s[2*ng+1][2], s[2*ng+1][3],
                         ah0, ah1, ah2, ah3, bh2, bh3);
                mma_bf16(s[2*ng+1][0], s[2*ng+1][1], s[2*ng+1][2], s[2*ng+1][3],
                         ah0, ah1, ah2, ah3, bl2, bl3);
                mma_bf16(s[2*ng+1][0], s[2*ng+1][1], s[2*ng+1][2], s[2*ng+1][3],
                         al0, al1, al2, al3, bh2, bh3);
            }
        }

        // ---- scale + causal mask + online softmax (registers only) ----
        const bool do_mask = (causal != 0) && (k0 + 63 > q0);
        float mx0 = -1e30f, mx1 = -1e30f;
#pragma unroll
        for (int nt = 0; nt < 8; nt++) {
            const int cg = k0 + nt * 8 + cb;
            float v0 = s[nt][0] * sm_scale, v1 = s[nt][1] * sm_scale;
            float v2 = s[nt][2] * sm_scale, v3 = s[nt][3] * sm_scale;
            if (do_mask) {
                if (cg     > rg0) v0 = -1e30f;
                if (cg + 1 > rg0) v1 = -1e30f;
                if (cg     > rg1) v2 = -1e30f;
                if (cg + 1 > rg1) v3 = -1e30f;
            }
            s[nt][0] = v0; s[nt][1] = v1; s[nt][2] = v2; s[nt][3] = v3;
            mx0 = fmaxf(mx0, fmaxf(v0, v1));
            mx1 = fmaxf(mx1, fmaxf(v2, v3));
        }
        mx0 = fmaxf(mx0, __shfl_xor_sync(0xffffffffu, mx0, 1));
        mx0 = fmaxf(mx0, __shfl_xor_sync(0xffffffffu, mx0, 2));
        mx1 = fmaxf(mx1, __shfl_xor_sync(0xffffffffu, mx1, 1));
        mx1 = fmaxf(mx1, __shfl_xor_sync(0xffffffffu, mx1, 2));

        const float mn0 = fmaxf(m0v, mx0), mn1 = fmaxf(m1v, mx1);
        const float alpha0 = __expf(m0v - mn0), alpha1 = __expf(m1v - mn1);
        float sum0 = 0.0f, sum1 = 0.0f;
#pragma unroll
        for (int nt = 0; nt < 8; nt++) {
            float p0 = __expf(s[nt][0] - mn0), p1 = __expf(s[nt][1] - mn0);
            float p2 = __expf(s[nt][2] - mn1), p3 = __expf(s[nt][3] - mn1);
            s[nt][0] = p0; s[nt][1] = p1; s[nt][2] = p2; s[nt][3] = p3;
            sum0 += p0 + p1; sum1 += p2 + p3;
        }
        sum0 += __shfl_xor_sync(0xffffffffu, sum0, 1);
        sum0 += __shfl_xor_sync(0xffffffffu, sum0, 2);
        sum1 += __shfl_xor_sync(0xffffffffu, sum1, 1);
        sum1 += __shfl_xor_sync(0xffffffffu, sum1, 2);
        l0 = l0 * alpha0 + sum0;
        l1 = l1 * alpha1 + sum1;
        m0v = mn0; m1v = mn1;

#pragma unroll
        for (int nt = 0; nt < 16; nt++) {
            o[nt][0] *= alpha0; o[nt][1] *= alpha0;
            o[nt][2] *= alpha1; o[nt][3] *= alpha1;
        }

        // ---- P -> bf16 hi/lo A-fragments (C-frag layout == A-frag layout) ----
        uint32_t ph[4][4], pl[4][4];
#pragma unroll
        for (int ks = 0; ks < 4; ks++) {
            pack_hilo(s[2*ks][0],   s[2*ks][1],   ph[ks][0], pl[ks][0]);
            pack_hilo(s[2*ks][2],   s[2*ks][3],   ph[ks][1], pl[ks][1]);
            pack_hilo(s[2*ks+1][0], s[2*ks+1][1], ph[ks][2], pl[ks][2]);
            pack_hilo(s[2*ks+1][2], s[2*ks+1][3], ph[ks][3], pl[ks][3]);
        }

        // ---- O += P V (bf16x3), V via ldmatrix.trans ----
#pragma unroll
        for (int ks = 0; ks < 4; ks++) {
            const uint32_t vrow = (uint32_t)(ks * 16) + v_rbase;
            const uint32_t vxr  = (vrow & 7) << 4;
#pragma unroll
            for (int ng = 0; ng < 8; ng++) {
                const uint32_t voff = vrow * 256 + (((uint32_t)(ng * 32) + v_cb) ^ vxr);
                uint32_t vh0, vh1, vh2, vh3, vl0, vl1, vl2, vl3;
                LDSM_X4_T(vh0, vh1, vh2, vh3, sb + ATT_VHI + voff);
                LDSM_X4_T(vl0, vl1, vl2, vl3, sb + ATT_VLO + voff);
                mma_bf16(o[2*ng][0], o[2*ng][1], o[2*ng][2], o[2*ng][3],
                         ph[ks][0], ph[ks][1], ph[ks][2], ph[ks][3], vh0, vh1);
                mma_bf16(o[2*ng][0], o[2*ng][1], o[2*ng][2], o[2*ng][3],
                         ph[ks][0], ph[ks][1], ph[ks][2], ph[ks][3], vl0, vl1);
                mma_bf16(o[2*ng][0], o[2*ng][1], o[2*ng][2], o[2*ng][3],
                         pl[ks][0], pl[ks][1], pl[ks][2], pl[ks][3], vh0, vh1);
                mma_bf16(o[2*ng+1][0], o[2*ng+1][1], o[2*ng+1][2], o[2*ng+1][3],
                         ph[ks][0], ph[ks][1], ph[ks][2], ph[ks][3], vh2, vh3);
                mma_bf16(o[2*ng+1][0], o[2*ng+1][1], o[2*ng+1][2], o[2*ng+1][3],
                         ph[ks][0], ph[ks][1], ph[ks][2], ph[ks][3], vl2, vl3);
                mma_bf16(o[2*ng+1][0], o[2*ng+1][1], o[2*ng+1][2], o[2*ng+1][3],
                         pl[ks][0], pl[ks][1], pl[ks][2], pl[ks][3], vh2, vh3);
            }
        }
    }

    // ---- epilogue: O /= l, write bf16 hi/lo ----
    const float inv0 = 1.0f / l0, inv1 = 1.0f / l1;
#pragma unroll
    for (int nt = 0; nt < 16; nt++) {
        const int col = h * HDIM + nt * 8 + cb;
        uint32_t hA, lA, hB, lB;
        pack_hilo(o[nt][0] * inv0, o[nt][1] * inv0, hA, lA);
        pack_hilo(o[nt][2] * inv1, o[nt][3] * inv1, hB, lB);
        *(uint32_t*)(g_ohi + (size_t)rg0 * D_MODEL + col) = hA;
        *(uint32_t*)(g_olo + (size_t)rg0 * D_MODEL + col) = lA;
        *(uint32_t*)(g_ohi + (size_t)rg1 * D_MODEL + col) = hB;
        *(uint32_t*)(g_olo + (size_t)rg1 * D_MODEL + col) = lB;
    }
}

// ---------------------------------------------------------------------------
// Launch
// ---------------------------------------------------------------------------
extern "C" void kernel_launch(void* const* d_in, const int* in_sizes, int n_in,
                              void* d_out, int out_size)
{
    const float* x  = (const float*)d_in[0];
    const float* wq = (const float*)d_in[1];
    const float* wk = (const float*)d_in[2];
    const float* wv = (const float*)d_in[3];
    const float* wo = (const float*)d_in[4];
    const int* causal = (const int*)d_in[5];
    float* out = (float*)d_out;

    __nv_bfloat16 *xhi, *xlo, *ohi, *olo;
    __nv_bfloat16 *qhi, *qlo, *khi, *klo, *vhi, *vlo;
    __nv_bfloat16 *wqh, *wql, *wkh, *wkl, *wvh, *wvl, *woh, *wol;
    cudaGetSymbolAddress((void**)&xhi, g_xhi);  cudaGetSymbolAddress((void**)&xlo, g_xlo);
    cudaGetSymbolAddress((void**)&ohi, g_ohi);  cudaGetSymbolAddress((void**)&olo, g_olo);
    cudaGetSymbolAddress((void**)&qhi, g_qhi);  cudaGetSymbolAddress((void**)&qlo, g_qlo);
    cudaGetSymbolAddress((void**)&khi, g_khi);  cudaGetSymbolAddress((void**)&klo, g_klo);
    cudaGetSymbolAddress((void**)&vhi, g_vhi);  cudaGetSymbolAddress((void**)&vlo, g_vlo);
    cudaGetSymbolAddress((void**)&wqh, g_wqhi); cudaGetSymbolAddress((void**)&wql, g_wqlo);
    cudaGetSymbolAddress((void**)&wkh, g_wkhi); cudaGetSymbolAddress((void**)&wkl, g_wklo);
    cudaGetSymbolAddress((void**)&wvh, g_wvhi); cudaGetSymbolAddress((void**)&wvl, g_wvlo);
    cudaGetSymbolAddress((void**)&woh, g_wohi); cudaGetSymbolAddress((void**)&wol, g_wolo);

    const int nx4 = S_LEN * D_MODEL / 4;
    const int nw4 = D_MODEL * D_MODEL / 4;

    split_kernel<<<nx4 / 256, 256>>>((const float4*)x,  (__nv_bfloat162*)xhi, (__nv_bfloat162*)xlo, nx4);
    split_kernel<<<nw4 / 256, 256>>>((const float4*)wq, (__nv_bfloat162*)wqh, (__nv_bfloat162*)wql, nw4);
    split_kernel<<<nw4 / 256, 256>>>((const float4*)wk, (__nv_bfloat162*)wkh, (__nv_bfloat162*)wkl, nw4);
    split_kernel<<<nw4 / 256, 256>>>((const float4*)wv, (__nv_bfloat162*)wvh, (__nv_bfloat162*)wvl, nw4);
    split_kernel<<<nw4 / 256, 256>>>((const float4*)wo, (__nv_bfloat162*)woh, (__nv_bfloat162*)wol, nw4);

    // QKV projections -> bf16 hi/lo outputs directly
    cudaFuncSetAttribute(gemm_mma_kernel<true>,  cudaFuncAttributeMaxDynamicSharedMemorySize, GEMM_SMEM);
    cudaFuncSetAttribute(gemm_mma_kernel<false>, cudaFuncAttributeMaxDynamicSharedMemorySize, GEMM_SMEM);
    dim3 gqkv(D_MODEL / 128, S_LEN / 128, 3);
    gemm_mma_kernel<true><<<gqkv, 256, GEMM_SMEM>>>(
        xhi, xlo, wqh, wql, wkh, wkl, wvh, wvl,
        nullptr, qhi, qlo, khi, klo, vhi, vlo);

    // Flash attention (tensor cores)
    cudaFuncSetAttribute(attn_mma_kernel, cudaFuncAttributeMaxDynamicSharedMemorySize, ATT_SMEM);
    attn_mma_kernel<<<dim3(S_LEN / 128, NHEADS), 256, ATT_SMEM>>>(causal);

    // Output projection -> fp32 out
    dim3 gout(D_MODEL / 128, S_LEN / 128, 1);
    gemm_mma_kernel<false><<<gout, 256, GEMM_SMEM>>>(
        ohi, olo, woh, wol, woh, wol, woh, wol,
        out, nullptr, nullptr, nullptr, nullptr, nullptr, nullptr);
}

// round 5
// speedup vs baseline: 3.2623x; 1.3626x over previous
#include <cuda_runtime.h>
#include <cuda_bf16.h>
#include <math.h>
#include <stdint.h>

#define S_LEN   4096
#define D_MODEL 2048
#define NHEADS  16
#define HDIM    128

// ---------------------------------------------------------------------------
// Scratch (device globals: allocation-guard-safe)
// ---------------------------------------------------------------------------
__device__ __nv_bfloat16 g_xhi[S_LEN * D_MODEL];
__device__ __nv_bfloat16 g_xlo[S_LEN * D_MODEL];
__device__ __nv_bfloat16 g_qhi[S_LEN * D_MODEL];
__device__ __nv_bfloat16 g_qlo[S_LEN * D_MODEL];
__device__ __nv_bfloat16 g_khi[S_LEN * D_MODEL];
__device__ __nv_bfloat16 g_klo[S_LEN * D_MODEL];
__device__ __nv_bfloat16 g_vhi[S_LEN * D_MODEL];
__device__ __nv_bfloat16 g_vlo[S_LEN * D_MODEL];
__device__ __nv_bfloat16 g_ohi[S_LEN * D_MODEL];
__device__ __nv_bfloat16 g_olo[S_LEN * D_MODEL];
__device__ __nv_bfloat16 g_wqhi[D_MODEL * D_MODEL];
__device__ __nv_bfloat16 g_wqlo[D_MODEL * D_MODEL];
__device__ __nv_bfloat16 g_wkhi[D_MODEL * D_MODEL];
__device__ __nv_bfloat16 g_wklo[D_MODEL * D_MODEL];
__device__ __nv_bfloat16 g_wvhi[D_MODEL * D_MODEL];
__device__ __nv_bfloat16 g_wvlo[D_MODEL * D_MODEL];
__device__ __nv_bfloat16 g_wohi[D_MODEL * D_MODEL];
__device__ __nv_bfloat16 g_wolo[D_MODEL * D_MODEL];

// ---------------------------------------------------------------------------
// Helpers
// ---------------------------------------------------------------------------
__device__ __forceinline__ uint32_t smem_u32(const void* p) {
    uint32_t a;
    asm("{ .reg .u64 t; cvta.to.shared.u64 t, %1; cvt.u32.u64 %0, t; }" : "=r"(a) : "l"(p));
    return a;
}

#define LDSM_X4(r0, r1, r2, r3, addr)                                         \
    asm volatile("ldmatrix.sync.aligned.m8n8.x4.shared.b16 {%0,%1,%2,%3}, [%4];" \
        : "=r"(r0), "=r"(r1), "=r"(r2), "=r"(r3) : "r"(addr))

#define LDSM_X4_T(r0, r1, r2, r3, addr)                                       \
    asm volatile("ldmatrix.sync.aligned.m8n8.x4.trans.shared.b16 {%0,%1,%2,%3}, [%4];" \
        : "=r"(r0), "=r"(r1), "=r"(r2), "=r"(r3) : "r"(addr))

#define CP_ASYNC16(dst, src)                                                  \
    asm volatile("cp.async.cg.shared.global [%0], [%1], 16;" :: "r"(dst), "l"(src))
#define CP_COMMIT() asm volatile("cp.async.commit_group;" ::: "memory")
#define CP_WAIT1()  asm volatile("cp.async.wait_group 1;" ::: "memory")

__device__ __forceinline__ void mma_bf16(float& c0, float& c1, float& c2, float& c3,
                                         uint32_t a0, uint32_t a1, uint32_t a2, uint32_t a3,
                                         uint32_t b0, uint32_t b1) {
    asm volatile(
        "mma.sync.aligned.m16n8k16.row.col.f32.bf16.bf16.f32 "
        "{%0,%1,%2,%3}, {%4,%5,%6,%7}, {%8,%9}, {%0,%1,%2,%3};"
        : "+f"(c0), "+f"(c1), "+f"(c2), "+f"(c3)
        : "r"(a0), "r"(a1), "r"(a2), "r"(a3), "r"(b0), "r"(b1));
}

__device__ __forceinline__ uint32_t pack2(__nv_bfloat16 a, __nv_bfloat16 b) {
    __nv_bfloat162 t(a, b);
    return *reinterpret_cast<uint32_t*>(&t);
}

__device__ __forceinline__ void pack_hilo(float x, float y, uint32_t& hi, uint32_t& lo) {
    __nv_bfloat16 hx = __float2bfloat16(x), hy = __float2bfloat16(y);
    float rx = x - __bfloat162float(hx), ry = y - __bfloat162float(hy);
    hi = pack2(hx, hy);
    lo = pack2(__float2bfloat16(rx), __float2bfloat16(ry));
}

// Swizzle for 64-byte-row tiles (GEMM, K-chunk 32)
__device__ __forceinline__ uint32_t swz64(uint32_t off) { return off ^ ((off >> 3) & 0x30); }
// Swizzle for 256-byte-row tiles (attention)
__device__ __forceinline__ uint32_t vswz(uint32_t off)  { return off ^ ((off >> 4) & 0x70); }

// ---------------------------------------------------------------------------
// fp32 -> bf16 hi/lo split
// ---------------------------------------------------------------------------
__global__ __launch_bounds__(256) void split_kernel(
    const float4* __restrict__ src, __nv_bfloat162* __restrict__ hi,
    __nv_bfloat162* __restrict__ lo, int n4)
{
    int i = blockIdx.x * blockDim.x + threadIdx.x;
    if (i >= n4) return;
    float4 v = src[i];
    uint32_t h0, l0, h1, l1;
    pack_hilo(v.x, v.y, h0, l0);
    pack_hilo(v.z, v.w, h1, l1);
    *reinterpret_cast<uint32_t*>(&hi[2 * i + 0]) = h0;
    *reinterpret_cast<uint32_t*>(&hi[2 * i + 1]) = h1;
    *reinterpret_cast<uint32_t*>(&lo[2 * i + 0]) = l0;
    *reinterpret_cast<uint32_t*>(&lo[2 * i + 1]) = l1;
}

// 4 weight splits fused into one launch (blockIdx.y selects weight)
__global__ __launch_bounds__(256) void split_w_kernel(
    const float4* __restrict__ w0, const float4* __restrict__ w1,
    const float4* __restrict__ w2, const float4* __restrict__ w3,
    __nv_bfloat162* __restrict__ h0p, __nv_bfloat162* __restrict__ l0p,
    __nv_bfloat162* __restrict__ h1p, __nv_bfloat162* __restrict__ l1p,
    __nv_bfloat162* __restrict__ h2p, __nv_bfloat162* __restrict__ l2p,
    __nv_bfloat162* __restrict__ h3p, __nv_bfloat162* __restrict__ l3p,
    int n4)
{
    int i = blockIdx.x * blockDim.x + threadIdx.x;
    if (i >= n4) return;
    const int s = blockIdx.y;
    const float4* src = (s == 0) ? w0 : (s == 1) ? w1 : (s == 2) ? w2 : w3;
    __nv_bfloat162* hi = (s == 0) ? h0p : (s == 1) ? h1p : (s == 2) ? h2p : h3p;
    __nv_bfloat162* lo = (s == 0) ? l0p : (s == 1) ? l1p : (s == 2) ? l2p : l3p;
    float4 v = src[i];
    uint32_t a0, b0, a1, b1;
    pack_hilo(v.x, v.y, a0, b0);
    pack_hilo(v.z, v.w, a1, b1);
    *reinterpret_cast<uint32_t*>(&hi[2 * i + 0]) = a0;
    *reinterpret_cast<uint32_t*>(&hi[2 * i + 1]) = a1;
    *reinterpret_cast<uint32_t*>(&lo[2 * i + 0]) = b0;
    *reinterpret_cast<uint32_t*>(&lo[2 * i + 1]) = b1;
}

// ---------------------------------------------------------------------------
// bf16x3 GEMM via mma.sync (NT), cp.async 2-stage pipeline, GBK=32.
// CTA: 128x128 tile, 256 threads (2m x 4n warps), warp tile 64x32.
// Stage = Ahi/Alo/Bhi/Blo 128x32 bf16 (8KB each) = 32KB; 2 stages = 64KB.
// ---------------------------------------------------------------------------
#define GBK2      32
#define GK_ITERS2 (D_MODEL / GBK2)   // 64
#define STAGE_B   32768
#define TO_AHI    0
#define TO_ALO    8192
#define TO_BHI    16384
#define TO_BLO    24576
#define GEMM_SMEM 65536

template<bool BF16OUT>
__global__ __launch_bounds__(256) void gemm_mma_kernel(
    const __nv_bfloat16* __restrict__ Ahi, const __nv_bfloat16* __restrict__ Alo,
    const __nv_bfloat16* __restrict__ Bhi0, const __nv_bfloat16* __restrict__ Blo0,
    const __nv_bfloat16* __restrict__ Bhi1, const __nv_bfloat16* __restrict__ Blo1,
    const __nv_bfloat16* __restrict__ Bhi2, const __nv_bfloat16* __restrict__ Blo2,
    float* __restrict__ C0,
    __nv_bfloat16* __restrict__ Chi0, __nv_bfloat16* __restrict__ Clo0,
    __nv_bfloat16* __restrict__ Chi1, __nv_bfloat16* __restrict__ Clo1,
    __nv_bfloat16* __restrict__ Chi2, __nv_bfloat16* __restrict__ Clo2)
{
    extern __shared__ char smem[];
    const uint32_t sbase = smem_u32(smem);
    const int tid  = threadIdx.x;
    const int wid  = tid >> 5;
    const int lane = tid & 31;

    const __nv_bfloat16* Bhi = (blockIdx.z == 0) ? Bhi0 : (blockIdx.z == 1) ? Bhi1 : Bhi2;
    const __nv_bfloat16* Blo = (blockIdx.z == 0) ? Blo0 : (blockIdx.z == 1) ? Blo1 : Blo2;
    __nv_bfloat16* Chi = (blockIdx.z == 0) ? Chi0 : (blockIdx.z == 1) ? Chi1 : Chi2;
    __nv_bfloat16* Clo = (blockIdx.z == 0) ? Clo0 : (blockIdx.z == 1) ? Clo1 : Clo2;

    const int m0 = blockIdx.y * 128;
    const int n0 = blockIdx.x * 128;

    const int warp_m = wid & 1;
    const int warp_n = wid >> 1;

    // Loader geometry: 512 chunks (16B) per tile-stage / 256 threads = 2 each
    const int lr0 = tid >> 2;            // row for chunk 0 (0..63)
    const int lc0 = tid & 3;             // chunk col
    // chunk 1: rows 64..127

    // Fragment geometry (64-byte rows)
    const uint32_t a_rowpart = (uint32_t)((warp_m * 64 + (lane & 15)) * 64 + (lane >> 4) * 16);
    const uint32_t b_rowpart = (uint32_t)((warp_n * 32 + (lane & 7) + ((lane >> 4) << 3)) * 64
                                          + ((lane >> 3) & 1) * 16);

    float acc[4][4][4];
#pragma unroll
    for (int i = 0; i < 4; i++)
#pragma unroll
        for (int j = 0; j < 4; j++)
#pragma unroll
            for (int t = 0; t < 4; t++) acc[i][j][t] = 0.0f;

    // ---- cp.async stage loader ----
    auto load_stage = [&](int it, int stage) {
        const int k0 = it * GBK2;
        const uint32_t sb = sbase + stage * STAGE_B;
        const __nv_bfloat16* srcs[4] = { Ahi, Alo, Bhi, Blo };
        const uint32_t offs[4] = { TO_AHI, TO_ALO, TO_BHI, TO_BLO };
        const int rows[4] = { m0, m0, n0, n0 };
#pragma unroll
        for (int t = 0; t < 4; t++) {
#pragma unroll
            for (int i = 0; i < 2; i++) {
                int r = lr0 + i * 64;
                const void* src = srcs[t] + (size_t)(rows[t] + r) * D_MODEL + k0 + lc0 * 8;
                uint32_t dst = sb + offs[t] + swz64((uint32_t)(r * 64 + lc0 * 16));
                CP_ASYNC16(dst, src);
            }
        }
    };

    load_stage(0, 0);
    CP_COMMIT();

    for (int it = 0; it < GK_ITERS2; it++) {
        const int cur = it & 1;
        if (it + 1 < GK_ITERS2) load_stage(it + 1, cur ^ 1);
        CP_COMMIT();
        CP_WAIT1();
        __syncthreads();

        const uint32_t sb = sbase + cur * STAGE_B;
#pragma unroll
        for (int ks = 0; ks < 2; ks++) {
            const uint32_t kbyte = (uint32_t)(ks * 32);

            uint32_t bh[8], bl[8];
            LDSM_X4(bh[0], bh[1], bh[2], bh[3], sb + TO_BHI + swz64(b_rowpart + kbyte));
            LDSM_X4(bh[4], bh[5], bh[6], bh[7], sb + TO_BHI + swz64(b_rowpart + 1024 + kbyte));
            LDSM_X4(bl[0], bl[1], bl[2], bl[3], sb + TO_BLO + swz64(b_rowpart + kbyte));
            LDSM_X4(bl[4], bl[5], bl[6], bl[7], sb + TO_BLO + swz64(b_rowpart + 1024 + kbyte));

            uint32_t af[16];
#pragma unroll
            for (int mt = 0; mt < 4; mt++) {
                uint32_t ad = sb + TO_AHI + swz64(a_rowpart + (uint32_t)(mt * 1024) + kbyte);
                LDSM_X4(af[mt * 4 + 0], af[mt * 4 + 1], af[mt * 4 + 2], af[mt * 4 + 3], ad);
            }
#pragma unroll
            for (int mt = 0; mt < 4; mt++)
#pragma unroll
                for (int nt = 0; nt < 4; nt++) {
                    mma_bf16(acc[mt][nt][0], acc[mt][nt][1], acc[mt][nt][2], acc[mt][nt][3],
                             af[mt*4+0], af[mt*4+1], af[mt*4+2], af[mt*4+3],
                             bh[nt*2+0], bh[nt*2+1]);
                    mma_bf16(acc[mt][nt][0], acc[mt][nt][1], acc[mt][nt][2], acc[mt][nt][3],
                             af[mt*4+0], af[mt*4+1], af[mt*4+2], af[mt*4+3],
                             bl[nt*2+0], bl[nt*2+1]);
                }
#pragma unroll
            for (int mt = 0; mt < 4; mt++) {
                uint32_t ad = sb + TO_ALO + swz64(a_rowpart + (uint32_t)(mt * 1024) + kbyte);
                LDSM_X4(af[mt * 4 + 0], af[mt * 4 + 1], af[mt * 4 + 2], af[mt * 4 + 3], ad);
            }
#pragma unroll
            for (int mt = 0; mt < 4; mt++)
#pragma unroll
                for (int nt = 0; nt < 4; nt++)
                    mma_bf16(acc[mt][nt][0], acc[mt][nt][1], acc[mt][nt][2], acc[mt][nt][3],
                             af[mt*4+0], af[mt*4+1], af[mt*4+2], af[mt*4+3],
                             bh[nt*2+0], bh[nt*2+1]);
        }
        __syncthreads();
    }

#pragma unroll
    for (int mt = 0; mt < 4; mt++) {
        int row = m0 + warp_m * 64 + mt * 16 + (lane >> 2);
#pragma unroll
        for (int nt = 0; nt < 4; nt++) {
            int col = n0 + warp_n * 32 + nt * 8 + (lane & 3) * 2;
            if (BF16OUT) {
                uint32_t h01, l01, h23, l23;
                pack_hilo(acc[mt][nt][0], acc[mt][nt][1], h01, l01);
                pack_hilo(acc[mt][nt][2], acc[mt][nt][3], h23, l23);
                *(uint32_t*)(Chi + (size_t)row * D_MODEL + col)       = h01;
                *(uint32_t*)(Clo + (size_t)row * D_MODEL + col)       = l01;
                *(uint32_t*)(Chi + (size_t)(row + 8) * D_MODEL + col) = h23;
                *(uint32_t*)(Clo + (size_t)(row + 8) * D_MODEL + col) = l23;
            } else {
                *(float2*)(C0 + (size_t)row * D_MODEL + col) =
                    make_float2(acc[mt][nt][0], acc[mt][nt][1]);
                *(float2*)(C0 + (size_t)(row + 8) * D_MODEL + col) =
                    make_float2(acc[mt][nt][2], acc[mt][nt][3]);
            }
        }
    }
}

// ---------------------------------------------------------------------------
// Flash attention on mma.sync, bf16x3, causal; cp.async 2-stage KV pipeline.
// Smem: Q hi/lo 64KB persistent + 2 x 64KB KV stages = 192KB, 1 CTA/SM.
// ---------------------------------------------------------------------------
#define ATT_QHI  0
#define ATT_QLO  32768
#define ATT_KV0  65536
#define KV_STAGE 65536
#define KVO_KHI  0
#define KVO_KLO  16384
#define KVO_VHI  32768
#define KVO_VLO  49152
#define ATT_SMEM (ATT_KV0 + 2 * KV_STAGE)   // 196608

__global__ __launch_bounds__(256, 1) void attn_mma_kernel(const int* __restrict__ causal_flag)
{
    extern __shared__ char smem[];
    const uint32_t sb = smem_u32(smem);
    const int tid  = threadIdx.x;
    const int w    = tid >> 5;
    const int lane = tid & 31;
    const int q0   = blockIdx.x * 128;
    const int h    = blockIdx.y;
    const int causal = *causal_flag;
    const float sm_scale = 0.08838834764831845f;

    // ---- Q hi/lo -> smem (persistent) ----
#pragma unroll
    for (int t = 0; t < 2; t++) {
        const __nv_bfloat16* src = t ? g_qlo : g_qhi;
        const uint32_t dst = t ? ATT_QLO : ATT_QHI;
#pragma unroll
        for (int i = 0; i < 8; i++) {
            int f = i * 256 + tid;
            int row = f >> 4, ch = f & 15;
            uint4 v = *(const uint4*)(src + (size_t)(q0 + row) * D_MODEL + h * HDIM + ch * 8);
            *(uint4*)(smem + dst + vswz((uint32_t)(row * 256 + ch * 16))) = v;
        }
    }

    // Loader geometry for KV: 1024 chunks per tile / 256 threads = 4 each
    const int kr0 = tid >> 4;     // rows 0..15 (+16 per i)
    const int kc0 = tid & 15;

    auto load_kv = [&](int kb, int stage) {
        const int k0 = kb * 64;
        const uint32_t base = ATT_KV0 + stage * KV_STAGE;
        const __nv_bfloat16* srcs[4] = { g_khi, g_klo, g_vhi, g_vlo };
        const uint32_t offs[4] = { KVO_KHI, KVO_KLO, KVO_VHI, KVO_VLO };
#pragma unroll
        for (int t = 0; t < 4; t++) {
#pragma unroll
            for (int i = 0; i < 4; i++) {
                int row = kr0 + i * 16;
                const void* src = srcs[t] + (size_t)(k0 + row) * D_MODEL + h * HDIM + kc0 * 8;
                uint32_t dst = sb + base + offs[t] + vswz((uint32_t)(row * 256 + kc0 * 16));
                CP_ASYNC16(dst, src);
            }
        }
    };

    // Per-thread fragment geometry
    const int rq  = lane >> 2;
    const int cb  = (lane & 3) * 2;
    const int rg0 = q0 + w * 8 + rq;
    const int rg1 = rg0 + 64;

    const uint32_t a_row = (uint32_t)((((lane >> 3) & 1) ? 64 + w * 8 : w * 8) + (lane & 7));
    const uint32_t a_xr  = (a_row & 7) << 4;
    const uint32_t a_cb  = ((lane >> 4) & 1) * 16;
    const uint32_t k_rbase = ((lane >> 4) & 1) * 8 + (lane & 7);
    const uint32_t k_cb    = ((lane >> 3) & 1) * 16;
    const uint32_t v_rbase = ((lane >> 3) & 1) * 8 + (lane & 7);
    const uint32_t v_cb    = ((lane >> 4) & 1) * 16;

    float o[16][4];
#pragma unroll
    for (int i = 0; i < 16; i++)
#pragma unroll
        for (int t = 0; t < 4; t++) o[i][t] = 0.0f;
    float m0v = -1e30f, m1v = -1e30f, l0 = 0.0f, l1 = 0.0f;

    const int kb_max = causal ? (q0 + 127) / 64 : (S_LEN / 64 - 1);

    load_kv(0, 0);
    CP_COMMIT();

    for (int kb = 0; kb <= kb_max; kb++) {
        const int k0 = kb * 64;
        const int cur = kb & 1;
        if (kb + 1 <= kb_max) load_kv(kb + 1, cur ^ 1);
        CP_COMMIT();
        CP_WAIT1();
        __syncthreads();

        const uint32_t kvb = ATT_KV0 + cur * KV_STAGE;

        // ---- S = Q K^T (bf16x3) ----
        float s[8][4];
#pragma unroll
        for (int i = 0; i < 8; i++)
#pragma unroll
            for (int t = 0; t < 4; t++) s[i][t] = 0.0f;

#pragma unroll
        for (int ks = 0; ks < 8; ks++) {
            const uint32_t aoff = a_row * 256 + (((uint32_t)(ks * 32) + a_cb) ^ a_xr);
            uint32_t ah0, ah1, ah2, ah3, al0, al1, al2, al3;
            LDSM_X4(ah0, ah1, ah2, ah3, sb + ATT_QHI + aoff);
            LDSM_X4(al0, al1, al2, al3, sb + ATT_QLO + aoff);
#pragma unroll
            for (int ng = 0; ng < 4; ng++) {
                const uint32_t krow = (uint32_t)(ng * 16) + k_rbase;
                const uint32_t koff = krow * 256 + (((uint32_t)(ks * 32) + k_cb) ^ ((krow & 7) << 4));
                uint32_t bh0, bh1, bh2, bh3, bl0, bl1, bl2, bl3;
                LDSM_X4(bh0, bh1, bh2, bh3, sb + kvb + KVO_KHI + koff);
                LDSM_X4(bl0, bl1, bl2, bl3, sb + kvb + KVO_KLO + koff);
                mma_bf16(s[2*ng][0], s[2*ng][1], s[2*ng][2], s[2*ng][3],
                         ah0, ah1, ah2, ah3, bh0, bh1);
                mma_bf16(s[2*ng][0], s[2*ng][1], s[2*ng][2], s[2*ng][3],
                         ah0, ah1, ah2, ah3, bl0, bl1);
                mma_bf16(s[2*ng][0], s[2*ng][1], s[2*ng][2], s[2*ng][3],
                         al0, al1, al2, al3, bh0, bh1);
                mma_bf16(s[2*ng+1][0], s[2*ng+1][1], s[2*ng+1][2], s[2*ng+1][3],
                         ah0, ah1, ah2, ah3, bh2, bh3);
                mma_bf16(s[2*ng+1][0], s[2*ng+1][1], s[2*ng+1][2], s[2*ng+1][3],
                         ah0, ah1, ah2, ah3, bl2, bl3);
                mma_bf16(s[2*ng+1][0], s[2*ng+1][1], s[2*ng+1][2], s[2*ng+1][3],
                         al0, al1, al2, al3, bh2, bh3);
            }
        }

        // ---- scale + causal mask + online softmax ----
        const bool do_mask = (causal != 0) && (k0 + 63 > q0);
        float mx0 = -1e30f, mx1 = -1e30f;
#pragma unroll
        for (int nt = 0; nt < 8; nt++) {
            const int cg = k0 + nt * 8 + cb;
            float v0 = s[nt][0] * sm_scale, v1 = s[nt][1] * sm_scale;
            float v2 = s[nt][2] * sm_scale, v3 = s[nt][3] * sm_scale;
            if (do_mask) {
                if (cg     > rg0) v0 = -1e30f;
                if (cg + 1 > rg0) v1 = -1e30f;
                if (cg     > rg1) v2 = -1e30f;
                if (cg + 1 > rg1) v3 = -1e30f;
            }
            s[nt][0] = v0; s[nt][1] = v1; s[nt][2] = v2; s[nt][3] = v3;
            mx0 = fmaxf(mx0, fmaxf(v0, v1));
            mx1 = fmaxf(mx1, fmaxf(v2, v3));
        }
        mx0 = fmaxf(mx0, __shfl_xor_sync(0xffffffffu, mx0, 1));
        mx0 = fmaxf(mx0, __shfl_xor_sync(0xffffffffu, mx0, 2));
        mx1 = fmaxf(mx1, __shfl_xor_sync(0xffffffffu, mx1, 1));
        mx1 = fmaxf(mx1, __shfl_xor_sync(0xffffffffu, mx1, 2));

        const float mn0 = fmaxf(m0v, mx0), mn1 = fmaxf(m1v, mx1);
        const float alpha0 = __expf(m0v - mn0), alpha1 = __expf(m1v - mn1);
        float sum0 = 0.0f, sum1 = 0.0f;
#pragma unroll
        for (int nt = 0; nt < 8; nt++) {
            float p0 = __expf(s[nt][0] - mn0), p1 = __expf(s[nt][1] - mn0);
            float p2 = __expf(s[nt][2] - mn1), p3 = __expf(s[nt][3] - mn1);
            s[nt][0] = p0; s[nt][1] = p1; s[nt][2] = p2; s[nt][3] = p3;
            sum0 += p0 + p1; sum1 += p2 + p3;
        }
        sum0 += __shfl_xor_sync(0xffffffffu, sum0, 1);
        sum0 += __shfl_xor_sync(0xffffffffu, sum0, 2);
        sum1 += __shfl_xor_sync(0xffffffffu, sum1, 1);
        sum1 += __shfl_xor_sync(0xffffffffu, sum1, 2);
        l0 = l0 * alpha0 + sum0;
        l1 = l1 * alpha1 + sum1;
        m0v = mn0; m1v = mn1;

#pragma unroll
        for (int nt = 0; nt < 16; nt++) {
            o[nt][0] *= alpha0; o[nt][1] *= alpha0;
            o[nt][2] *= alpha1; o[nt][3] *= alpha1;
        }

        // ---- P -> bf16 hi/lo A-fragments ----
        uint32_t ph[4][4], pl[4][4];
#pragma unroll
        for (int ks = 0; ks < 4; ks++) {
            pack_hilo(s[2*ks][0],   s[2*ks][1],   ph[ks][0], pl[ks][0]);
            pack_hilo(s[2*ks][2],   s[2*ks][3],   ph[ks][1], pl[ks][1]);
            pack_hilo(s[2*ks+1][0], s[2*ks+1][1], ph[ks][2], pl[ks][2]);
            pack_hilo(s[2*ks+1][2], s[2*ks+1][3], ph[ks][3], pl[ks][3]);
        }

        // ---- O += P V (bf16x3), V via ldmatrix.trans ----
#pragma unroll
        for (int ks = 0; ks < 4; ks++) {
            const uint32_t vrow = (uint32_t)(ks * 16) + v_rbase;
            const uint32_t vxr  = (vrow & 7) << 4;
#pragma unroll
            for (int ng = 0; ng < 8; ng++) {
                const uint32_t voff = vrow * 256 + (((uint32_t)(ng * 32) + v_cb) ^ vxr);
                uint32_t vh0, vh1, vh2, vh3, vl0, vl1, vl2, vl3;
                LDSM_X4_T(vh0, vh1, vh2, vh3, sb + kvb + KVO_VHI + voff);
                LDSM_X4_T(vl0, vl1, vl2, vl3, sb + kvb + KVO_VLO + voff);
                mma_bf16(o[2*ng][0], o[2*ng][1], o[2*ng][2], o[2*ng][3],
                         ph[ks][0], ph[ks][1], ph[ks][2], ph[ks][3], vh0, vh1);
                mma_bf16(o[2*ng][0], o[2*ng][1], o[2*ng][2], o[2*ng][3],
                         ph[ks][0], ph[ks][1], ph[ks][2], ph[ks][3], vl0, vl1);
                mma_bf16(o[2*ng][0], o[2*ng][1], o[2*ng][2], o[2*ng][3],
                         pl[ks][0], pl[ks][1], pl[ks][2], pl[ks][3], vh0, vh1);
                mma_bf16(o[2*ng+1][0], o[2*ng+1][1], o[2*ng+1][2], o[2*ng+1][3],
                         ph[ks][0], ph[ks][1], ph[ks][2], ph[ks][3], vh2, vh3);
                mma_bf16(o[2*ng+1][0], o[2*ng+1][1], o[2*ng+1][2], o[2*ng+1][3],
                         ph[ks][0], ph[ks][1], ph[ks][2], ph[ks][3], vl2, vl3);
                mma_bf16(o[2*ng+1][0], o[2*ng+1][1], o[2*ng+1][2], o[2*ng+1][3],
                         pl[ks][0], pl[ks][1], pl[ks][2], pl[ks][3], vh2, vh3);
            }
        }
        __syncthreads();
    }

    // ---- epilogue ----
    const float inv0 = 1.0f / l0, inv1 = 1.0f / l1;
#pragma unroll
    for (int nt = 0; nt < 16; nt++) {
        const int col = h * HDIM + nt * 8 + cb;
        uint32_t hA, lA, hB, lB;
        pack_hilo(o[nt][0] * inv0, o[nt][1] * inv0, hA, lA);
        pack_hilo(o[nt][2] * inv1, o[nt][3] * inv1, hB, lB);
        *(uint32_t*)(g_ohi + (size_t)rg0 * D_MODEL + col) = hA;
        *(uint32_t*)(g_olo + (size_t)rg0 * D_MODEL + col) = lA;
        *(uint32_t*)(g_ohi + (size_t)rg1 * D_MODEL + col) = hB;
        *(uint32_t*)(g_olo + (size_t)rg1 * D_MODEL + col) = lB;
    }
}

// ---------------------------------------------------------------------------
// Launch
// ---------------------------------------------------------------------------
extern "C" void kernel_launch(void* const* d_in, const int* in_sizes, int n_in,
                              void* d_out, int out_size)
{
    const float* x  = (const float*)d_in[0];
    const float* wq = (const float*)d_in[1];
    const float* wk = (const float*)d_in[2];
    const float* wv = (const float*)d_in[3];
    const float* wo = (const float*)d_in[4];
    const int* causal = (const int*)d_in[5];
    float* out = (float*)d_out;

    __nv_bfloat16 *xhi, *xlo, *ohi, *olo;
    __nv_bfloat16 *qhi, *qlo, *khi, *klo, *vhi, *vlo;
    __nv_bfloat16 *wqh, *wql, *wkh, *wkl, *wvh, *wvl, *woh, *wol;
    cudaGetSymbolAddress((void**)&xhi, g_xhi);  cudaGetSymbolAddress((void**)&xlo, g_xlo);
    cudaGetSymbolAddress((void**)&ohi, g_ohi);  cudaGetSymbolAddress((void**)&olo, g_olo);
    cudaGetSymbolAddress((void**)&qhi, g_qhi);  cudaGetSymbolAddress((void**)&qlo, g_qlo);
    cudaGetSymbolAddress((void**)&khi, g_khi);  cudaGetSymbolAddress((void**)&klo, g_klo);
    cudaGetSymbolAddress((void**)&vhi, g_vhi);  cudaGetSymbolAddress((void**)&vlo, g_vlo);
    cudaGetSymbolAddress((void**)&wqh, g_wqhi); cudaGetSymbolAddress((void**)&wql, g_wqlo);
    cudaGetSymbolAddress((void**)&wkh, g_wkhi); cudaGetSymbolAddress((void**)&wkl, g_wklo);
    cudaGetSymbolAddress((void**)&wvh, g_wvhi); cudaGetSymbolAddress((void**)&wvl, g_wvlo);
    cudaGetSymbolAddress((void**)&woh, g_wohi); cudaGetSymbolAddress((void**)&wol, g_wolo);

    const int nx4 = S_LEN * D_MODEL / 4;
    const int nw4 = D_MODEL * D_MODEL / 4;

    split_kernel<<<nx4 / 256, 256>>>((const float4*)x, (__nv_bfloat162*)xhi, (__nv_bfloat162*)xlo, nx4);
    split_w_kernel<<<dim3(nw4 / 256, 4), 256>>>(
        (const float4*)wq, (const float4*)wk, (const float4*)wv, (const float4*)wo,
        (__nv_bfloat162*)wqh, (__nv_bfloat162*)wql,
        (__nv_bfloat162*)wkh, (__nv_bfloat162*)wkl,
        (__nv_bfloat162*)wvh, (__nv_bfloat162*)wvl,
        (__nv_bfloat162*)woh, (__nv_bfloat162*)wol, nw4);

    // QKV projections -> bf16 hi/lo outputs directly
    cudaFuncSetAttribute(gemm_mma_kernel<true>,  cudaFuncAttributeMaxDynamicSharedMemorySize, GEMM_SMEM);
    cudaFuncSetAttribute(gemm_mma_kernel<false>, cudaFuncAttributeMaxDynamicSharedMemorySize, GEMM_SMEM);
    dim3 gqkv(D_MODEL / 128, S_LEN / 128, 3);
    gemm_mma_kernel<true><<<gqkv, 256, GEMM_SMEM>>>(
        xhi, xlo, wqh, wql, wkh, wkl, wvh, wvl,
        nullptr, qhi, qlo, khi, klo, vhi, vlo);

    // Flash attention (tensor cores, cp.async pipeline)
    cudaFuncSetAttribute(attn_mma_kernel, cudaFuncAttributeMaxDynamicSharedMemorySize, ATT_SMEM);
    attn_mma_kernel<<<dim3(S_LEN / 128, NHEADS), 256, ATT_SMEM>>>(causal);

    // Output projection -> fp32 out
    dim3 gout(D_MODEL / 128, S_LEN / 128, 1);
    gemm_mma_kernel<false><<<gout, 256, GEMM_SMEM>>>(
        ohi, olo, woh, wol, woh, wol, woh, wol,
        out, nullptr, nullptr, nullptr, nullptr, nullptr, nullptr);
}

// round 6
// speedup vs baseline: 3.3423x; 1.0245x over previous
#include <cuda_runtime.h>
#include <cuda_bf16.h>
#include <math.h>
#include <stdint.h>

#define S_LEN   4096
#define D_MODEL 2048
#define NHEADS  16
#define HDIM    128

// ---------------------------------------------------------------------------
// Scratch (device globals: allocation-guard-safe)
// ---------------------------------------------------------------------------
__device__ __nv_bfloat16 g_xhi[S_LEN * D_MODEL];
__device__ __nv_bfloat16 g_xlo[S_LEN * D_MODEL];
__device__ __nv_bfloat16 g_qhi[S_LEN * D_MODEL];
__device__ __nv_bfloat16 g_qlo[S_LEN * D_MODEL];
__device__ __nv_bfloat16 g_khi[S_LEN * D_MODEL];
__device__ __nv_bfloat16 g_klo[S_LEN * D_MODEL];
__device__ __nv_bfloat16 g_vhi[S_LEN * D_MODEL];
__device__ __nv_bfloat16 g_vlo[S_LEN * D_MODEL];
__device__ __nv_bfloat16 g_ohi[S_LEN * D_MODEL];
__device__ __nv_bfloat16 g_olo[S_LEN * D_MODEL];
__device__ __nv_bfloat16 g_wqhi[D_MODEL * D_MODEL];
__device__ __nv_bfloat16 g_wqlo[D_MODEL * D_MODEL];
__device__ __nv_bfloat16 g_wkhi[D_MODEL * D_MODEL];
__device__ __nv_bfloat16 g_wklo[D_MODEL * D_MODEL];
__device__ __nv_bfloat16 g_wvhi[D_MODEL * D_MODEL];
__device__ __nv_bfloat16 g_wvlo[D_MODEL * D_MODEL];
__device__ __nv_bfloat16 g_wohi[D_MODEL * D_MODEL];
__device__ __nv_bfloat16 g_wolo[D_MODEL * D_MODEL];

// ---------------------------------------------------------------------------
// Helpers
// ---------------------------------------------------------------------------
__device__ __forceinline__ uint32_t smem_u32(const void* p) {
    uint32_t a;
    asm("{ .reg .u64 t; cvta.to.shared.u64 t, %1; cvt.u32.u64 %0, t; }" : "=r"(a) : "l"(p));
    return a;
}

#define LDSM_X4(r0, r1, r2, r3, addr)                                         \
    asm volatile("ldmatrix.sync.aligned.m8n8.x4.shared.b16 {%0,%1,%2,%3}, [%4];" \
        : "=r"(r0), "=r"(r1), "=r"(r2), "=r"(r3) : "r"(addr))

#define LDSM_X4_T(r0, r1, r2, r3, addr)                                       \
    asm volatile("ldmatrix.sync.aligned.m8n8.x4.trans.shared.b16 {%0,%1,%2,%3}, [%4];" \
        : "=r"(r0), "=r"(r1), "=r"(r2), "=r"(r3) : "r"(addr))

#define CP_ASYNC16(dst, src)                                                  \
    asm volatile("cp.async.cg.shared.global [%0], [%1], 16;" :: "r"(dst), "l"(src))
#define CP_COMMIT() asm volatile("cp.async.commit_group;" ::: "memory")
#define CP_WAIT0()  asm volatile("cp.async.wait_group 0;" ::: "memory")

__device__ __forceinline__ void mma_bf16(float& c0, float& c1, float& c2, float& c3,
                                         uint32_t a0, uint32_t a1, uint32_t a2, uint32_t a3,
                                         uint32_t b0, uint32_t b1) {
    asm volatile(
        "mma.sync.aligned.m16n8k16.row.col.f32.bf16.bf16.f32 "
        "{%0,%1,%2,%3}, {%4,%5,%6,%7}, {%8,%9}, {%0,%1,%2,%3};"
        : "+f"(c0), "+f"(c1), "+f"(c2), "+f"(c3)
        : "r"(a0), "r"(a1), "r"(a2), "r"(a3), "r"(b0), "r"(b1));
}

__device__ __forceinline__ uint32_t pack2(__nv_bfloat16 a, __nv_bfloat16 b) {
    __nv_bfloat162 t(a, b);
    return *reinterpret_cast<uint32_t*>(&t);
}

__device__ __forceinline__ void pack_hilo(float x, float y, uint32_t& hi, uint32_t& lo) {
    __nv_bfloat16 hx = __float2bfloat16(x), hy = __float2bfloat16(y);
    float rx = x - __bfloat162float(hx), ry = y - __bfloat162float(hy);
    hi = pack2(hx, hy);
    lo = pack2(__float2bfloat16(rx), __float2bfloat16(ry));
}

__device__ __forceinline__ uint32_t swz64(uint32_t off) { return off ^ ((off >> 3) & 0x30); }
__device__ __forceinline__ uint32_t vswz(uint32_t off)  { return off ^ ((off >> 4) & 0x70); }

// ---------------------------------------------------------------------------
// fp32 -> bf16 hi/lo split
// ---------------------------------------------------------------------------
__global__ __launch_bounds__(256) void split_kernel(
    const float4* __restrict__ src, __nv_bfloat162* __restrict__ hi,
    __nv_bfloat162* __restrict__ lo, int n4)
{
    int i = blockIdx.x * blockDim.x + threadIdx.x;
    if (i >= n4) return;
    float4 v = src[i];
    uint32_t h0, l0, h1, l1;
    pack_hilo(v.x, v.y, h0, l0);
    pack_hilo(v.z, v.w, h1, l1);
    *reinterpret_cast<uint32_t*>(&hi[2 * i + 0]) = h0;
    *reinterpret_cast<uint32_t*>(&hi[2 * i + 1]) = h1;
    *reinterpret_cast<uint32_t*>(&lo[2 * i + 0]) = l0;
    *reinterpret_cast<uint32_t*>(&lo[2 * i + 1]) = l1;
}

__global__ __launch_bounds__(256) void split_w_kernel(
    const float4* __restrict__ w0, const float4* __restrict__ w1,
    const float4* __restrict__ w2, const float4* __restrict__ w3,
    __nv_bfloat162* __restrict__ h0p, __nv_bfloat162* __restrict__ l0p,
    __nv_bfloat162* __restrict__ h1p, __nv_bfloat162* __restrict__ l1p,
    __nv_bfloat162* __restrict__ h2p, __nv_bfloat162* __restrict__ l2p,
    __nv_bfloat162* __restrict__ h3p, __nv_bfloat162* __restrict__ l3p,
    int n4)
{
    int i = blockIdx.x * blockDim.x + threadIdx.x;
    if (i >= n4) return;
    const int s = blockIdx.y;
    const float4* src = (s == 0) ? w0 : (s == 1) ? w1 : (s == 2) ? w2 : w3;
    __nv_bfloat162* hi = (s == 0) ? h0p : (s == 1) ? h1p : (s == 2) ? h2p : h3p;
    __nv_bfloat162* lo = (s == 0) ? l0p : (s == 1) ? l1p : (s == 2) ? l2p : l3p;
    float4 v = src[i];
    uint32_t a0, b0, a1, b1;
    pack_hilo(v.x, v.y, a0, b0);
    pack_hilo(v.z, v.w, a1, b1);
    *reinterpret_cast<uint32_t*>(&hi[2 * i + 0]) = a0;
    *reinterpret_cast<uint32_t*>(&hi[2 * i + 1]) = a1;
    *reinterpret_cast<uint32_t*>(&lo[2 * i + 0]) = b0;
    *reinterpret_cast<uint32_t*>(&lo[2 * i + 1]) = b1;
}

// ---------------------------------------------------------------------------
// bf16x3 GEMM, cp.async 2-stage, single barrier/iter, pass-separated MMAs.
// ---------------------------------------------------------------------------
#define GBK2      32
#define GK_ITERS2 (D_MODEL / GBK2)
#define STAGE_B   32768
#define TO_AHI    0
#define TO_ALO    8192
#define TO_BHI    16384
#define TO_BLO    24576
#define GEMM_SMEM 65536

template<bool BF16OUT>
__global__ __launch_bounds__(256) void gemm_mma_kernel(
    const __nv_bfloat16* __restrict__ Ahi, const __nv_bfloat16* __restrict__ Alo,
    const __nv_bfloat16* __restrict__ Bhi0, const __nv_bfloat16* __restrict__ Blo0,
    const __nv_bfloat16* __restrict__ Bhi1, const __nv_bfloat16* __restrict__ Blo1,
    const __nv_bfloat16* __restrict__ Bhi2, const __nv_bfloat16* __restrict__ Blo2,
    float* __restrict__ C0,
    __nv_bfloat16* __restrict__ Chi0, __nv_bfloat16* __restrict__ Clo0,
    __nv_bfloat16* __restrict__ Chi1, __nv_bfloat16* __restrict__ Clo1,
    __nv_bfloat16* __restrict__ Chi2, __nv_bfloat16* __restrict__ Clo2)
{
    extern __shared__ char smem[];
    const uint32_t sbase = smem_u32(smem);
    const int tid  = threadIdx.x;
    const int wid  = tid >> 5;
    const int lane = tid & 31;

    const __nv_bfloat16* Bhi = (blockIdx.z == 0) ? Bhi0 : (blockIdx.z == 1) ? Bhi1 : Bhi2;
    const __nv_bfloat16* Blo = (blockIdx.z == 0) ? Blo0 : (blockIdx.z == 1) ? Blo1 : Blo2;
    __nv_bfloat16* Chi = (blockIdx.z == 0) ? Chi0 : (blockIdx.z == 1) ? Chi1 : Chi2;
    __nv_bfloat16* Clo = (blockIdx.z == 0) ? Clo0 : (blockIdx.z == 1) ? Clo1 : Clo2;

    const int m0 = blockIdx.y * 128;
    const int n0 = blockIdx.x * 128;

    const int warp_m = wid & 1;
    const int warp_n = wid >> 1;

    const int lr0 = tid >> 2;
    const int lc0 = tid & 3;

    const uint32_t a_rowpart = (uint32_t)((warp_m * 64 + (lane & 15)) * 64 + (lane >> 4) * 16);
    const uint32_t b_rowpart = (uint32_t)((warp_n * 32 + (lane & 7) + ((lane >> 4) << 3)) * 64
                                          + ((lane >> 3) & 1) * 16);

    float acc[4][4][4];
#pragma unroll
    for (int i = 0; i < 4; i++)
#pragma unroll
        for (int j = 0; j < 4; j++)
#pragma unroll
            for (int t = 0; t < 4; t++) acc[i][j][t] = 0.0f;

    auto load_stage = [&](int it, int stage) {
        const int k0 = it * GBK2;
        const uint32_t sb = sbase + stage * STAGE_B;
        const __nv_bfloat16* srcs[4] = { Ahi, Alo, Bhi, Blo };
        const uint32_t offs[4] = { TO_AHI, TO_ALO, TO_BHI, TO_BLO };
        const int rows[4] = { m0, m0, n0, n0 };
#pragma unroll
        for (int t = 0; t < 4; t++) {
#pragma unroll
            for (int i = 0; i < 2; i++) {
                int r = lr0 + i * 64;
                const void* src = srcs[t] + (size_t)(rows[t] + r) * D_MODEL + k0 + lc0 * 8;
                uint32_t dst = sb + offs[t] + swz64((uint32_t)(r * 64 + lc0 * 16));
                CP_ASYNC16(dst, src);
            }
        }
    };

    load_stage(0, 0);
    CP_COMMIT();

    for (int it = 0; it < GK_ITERS2; it++) {
        const int cur = it & 1;
        CP_WAIT0();
        __syncthreads();
        if (it + 1 < GK_ITERS2) { load_stage(it + 1, cur ^ 1); CP_COMMIT(); }

        const uint32_t sb = sbase + cur * STAGE_B;
#pragma unroll
        for (int ks = 0; ks < 2; ks++) {
            const uint32_t kbyte = (uint32_t)(ks * 32);

            uint32_t bh[8], bl[8];
            LDSM_X4(bh[0], bh[1], bh[2], bh[3], sb + TO_BHI + swz64(b_rowpart + kbyte));
            LDSM_X4(bh[4], bh[5], bh[6], bh[7], sb + TO_BHI + swz64(b_rowpart + 1024 + kbyte));
            LDSM_X4(bl[0], bl[1], bl[2], bl[3], sb + TO_BLO + swz64(b_rowpart + kbyte));
            LDSM_X4(bl[4], bl[5], bl[6], bl[7], sb + TO_BLO + swz64(b_rowpart + 1024 + kbyte));

            uint32_t af[16];
#pragma unroll
            for (int mt = 0; mt < 4; mt++) {
                uint32_t ad = sb + TO_AHI + swz64(a_rowpart + (uint32_t)(mt * 1024) + kbyte);
                LDSM_X4(af[mt * 4 + 0], af[mt * 4 + 1], af[mt * 4 + 2], af[mt * 4 + 3], ad);
            }
            // pass 1: hi*hi (16 independent accumulators)
#pragma unroll
            for (int mt = 0; mt < 4; mt++)
#pragma unroll
                for (int nt = 0; nt < 4; nt++)
                    mma_bf16(acc[mt][nt][0], acc[mt][nt][1], acc[mt][nt][2], acc[mt][nt][3],
                             af[mt*4+0], af[mt*4+1], af[mt*4+2], af[mt*4+3],
                             bh[nt*2+0], bh[nt*2+1]);
            // pass 2: hi*lo
#pragma unroll
            for (int mt = 0; mt < 4; mt++)
#pragma unroll
                for (int nt = 0; nt < 4; nt++)
                    mma_bf16(acc[mt][nt][0], acc[mt][nt][1], acc[mt][nt][2], acc[mt][nt][3],
                             af[mt*4+0], af[mt*4+1], af[mt*4+2], af[mt*4+3],
                             bl[nt*2+0], bl[nt*2+1]);
            // pass 3: lo*hi
#pragma unroll
            for (int mt = 0; mt < 4; mt++) {
                uint32_t ad = sb + TO_ALO + swz64(a_rowpart + (uint32_t)(mt * 1024) + kbyte);
                LDSM_X4(af[mt * 4 + 0], af[mt * 4 + 1], af[mt * 4 + 2], af[mt * 4 + 3], ad);
            }
#pragma unroll
            for (int mt = 0; mt < 4; mt++)
#pragma unroll
                for (int nt = 0; nt < 4; nt++)
                    mma_bf16(acc[mt][nt][0], acc[mt][nt][1], acc[mt][nt][2], acc[mt][nt][3],
                             af[mt*4+0], af[mt*4+1], af[mt*4+2], af[mt*4+3],
                             bh[nt*2+0], bh[nt*2+1]);
        }
    }

#pragma unroll
    for (int mt = 0; mt < 4; mt++) {
        int row = m0 + warp_m * 64 + mt * 16 + (lane >> 2);
#pragma unroll
        for (int nt = 0; nt < 4; nt++) {
            int col = n0 + warp_n * 32 + nt * 8 + (lane & 3) * 2;
            if (BF16OUT) {
                uint32_t h01, l01, h23, l23;
                pack_hilo(acc[mt][nt][0], acc[mt][nt][1], h01, l01);
                pack_hilo(acc[mt][nt][2], acc[mt][nt][3], h23, l23);
                *(uint32_t*)(Chi + (size_t)row * D_MODEL + col)       = h01;
                *(uint32_t*)(Clo + (size_t)row * D_MODEL + col)       = l01;
                *(uint32_t*)(Chi + (size_t)(row + 8) * D_MODEL + col) = h23;
                *(uint32_t*)(Clo + (size_t)(row + 8) * D_MODEL + col) = l23;
            } else {
                *(float2*)(C0 + (size_t)row * D_MODEL + col) =
                    make_float2(acc[mt][nt][0], acc[mt][nt][1]);
                *(float2*)(C0 + (size_t)(row + 8) * D_MODEL + col) =
                    make_float2(acc[mt][nt][2], acc[mt][nt][3]);
            }
        }
    }
}

// ---------------------------------------------------------------------------
// Flash attention, bf16x3, causal; single-barrier cp.async pipeline;
// dependency-spread MMA passes; reversed q-block order for causal balance.
// ---------------------------------------------------------------------------
#define ATT_QHI  0
#define ATT_QLO  32768
#define ATT_KV0  65536
#define KV_STAGE 65536
#define KVO_KHI  0
#define KVO_KLO  16384
#define KVO_VHI  32768
#define KVO_VLO  49152
#define ATT_SMEM (ATT_KV0 + 2 * KV_STAGE)

__global__ __launch_bounds__(256, 1) void attn_mma_kernel(const int* __restrict__ causal_flag)
{
    extern __shared__ char smem[];
    const uint32_t sb = smem_u32(smem);
    const int tid  = threadIdx.x;
    const int w    = tid >> 5;
    const int lane = tid & 31;
    const int q0   = (gridDim.x - 1 - blockIdx.x) * 128;   // heavy blocks first
    const int h    = blockIdx.y;
    const int causal = *causal_flag;
    const float sm_scale = 0.08838834764831845f;

    // ---- Q hi/lo -> smem (persistent) ----
#pragma unroll
    for (int t = 0; t < 2; t++) {
        const __nv_bfloat16* src = t ? g_qlo : g_qhi;
        const uint32_t dst = t ? ATT_QLO : ATT_QHI;
#pragma unroll
        for (int i = 0; i < 8; i++) {
            int f = i * 256 + tid;
            int row = f >> 4, ch = f & 15;
            uint4 v = *(const uint4*)(src + (size_t)(q0 + row) * D_MODEL + h * HDIM + ch * 8);
            *(uint4*)(smem + dst + vswz((uint32_t)(row * 256 + ch * 16))) = v;
        }
    }

    const int kr0 = tid >> 4;
    const int kc0 = tid & 15;

    auto load_kv = [&](int kb, int stage) {
        const int k0 = kb * 64;
        const uint32_t base = ATT_KV0 + stage * KV_STAGE;
        const __nv_bfloat16* srcs[4] = { g_khi, g_klo, g_vhi, g_vlo };
        const uint32_t offs[4] = { KVO_KHI, KVO_KLO, KVO_VHI, KVO_VLO };
#pragma unroll
        for (int t = 0; t < 4; t++) {
#pragma unroll
            for (int i = 0; i < 4; i++) {
                int row = kr0 + i * 16;
                const void* src = srcs[t] + (size_t)(k0 + row) * D_MODEL + h * HDIM + kc0 * 8;
                uint32_t dst = sb + base + offs[t] + vswz((uint32_t)(row * 256 + kc0 * 16));
                CP_ASYNC16(dst, src);
            }
        }
    };

    const int rq  = lane >> 2;
    const int cb  = (lane & 3) * 2;
    const int rg0 = q0 + w * 8 + rq;
    const int rg1 = rg0 + 64;

    const uint32_t a_row = (uint32_t)((((lane >> 3) & 1) ? 64 + w * 8 : w * 8) + (lane & 7));
    const uint32_t a_xr  = (a_row & 7) << 4;
    const uint32_t a_cb  = ((lane >> 4) & 1) * 16;
    const uint32_t k_rbase = ((lane >> 4) & 1) * 8 + (lane & 7);
    const uint32_t k_cb    = ((lane >> 3) & 1) * 16;
    const uint32_t v_rbase = ((lane >> 3) & 1) * 8 + (lane & 7);
    const uint32_t v_cb    = ((lane >> 4) & 1) * 16;

    float o[16][4];
#pragma unroll
    for (int i = 0; i < 16; i++)
#pragma unroll
        for (int t = 0; t < 4; t++) o[i][t] = 0.0f;
    float m0v = -1e30f, m1v = -1e30f, l0 = 0.0f, l1 = 0.0f;

    const int kb_max = causal ? (q0 + 127) / 64 : (S_LEN / 64 - 1);

    load_kv(0, 0);
    CP_COMMIT();

    for (int kb = 0; kb <= kb_max; kb++) {
        const int k0 = kb * 64;
        const int cur = kb & 1;
        CP_WAIT0();
        __syncthreads();
        if (kb + 1 <= kb_max) { load_kv(kb + 1, cur ^ 1); CP_COMMIT(); }

        const uint32_t kvb = ATT_KV0 + cur * KV_STAGE;

        // ---- S = Q K^T (bf16x3), dependency-spread passes ----
        float s[8][4];
#pragma unroll
        for (int i = 0; i < 8; i++)
#pragma unroll
            for (int t = 0; t < 4; t++) s[i][t] = 0.0f;

#pragma unroll
        for (int ks = 0; ks < 8; ks++) {
            const uint32_t aoff = a_row * 256 + (((uint32_t)(ks * 32) + a_cb) ^ a_xr);
            uint32_t ah0, ah1, ah2, ah3, al0, al1, al2, al3;
            LDSM_X4(ah0, ah1, ah2, ah3, sb + ATT_QHI + aoff);
            LDSM_X4(al0, al1, al2, al3, sb + ATT_QLO + aoff);

            uint32_t bh[16], bl[16];
#pragma unroll
            for (int ng = 0; ng < 4; ng++) {
                const uint32_t krow = (uint32_t)(ng * 16) + k_rbase;
                const uint32_t koff = krow * 256 + (((uint32_t)(ks * 32) + k_cb) ^ ((krow & 7) << 4));
                LDSM_X4(bh[4*ng+0], bh[4*ng+1], bh[4*ng+2], bh[4*ng+3], sb + kvb + KVO_KHI + koff);
                LDSM_X4(bl[4*ng+0], bl[4*ng+1], bl[4*ng+2], bl[4*ng+3], sb + kvb + KVO_KLO + koff);
            }
            // pass hh (8 independent)
#pragma unroll
            for (int ng = 0; ng < 4; ng++) {
                mma_bf16(s[2*ng][0], s[2*ng][1], s[2*ng][2], s[2*ng][3],
                         ah0, ah1, ah2, ah3, bh[4*ng+0], bh[4*ng+1]);
                mma_bf16(s[2*ng+1][0], s[2*ng+1][1], s[2*ng+1][2], s[2*ng+1][3],
                         ah0, ah1, ah2, ah3, bh[4*ng+2], bh[4*ng+3]);
            }
            // pass hl
#pragma unroll
            for (int ng = 0; ng < 4; ng++) {
                mma_bf16(s[2*ng][0], s[2*ng][1], s[2*ng][2], s[2*ng][3],
                         ah0, ah1, ah2, ah3, bl[4*ng+0], bl[4*ng+1]);
                mma_bf16(s[2*ng+1][0], s[2*ng+1][1], s[2*ng+1][2], s[2*ng+1][3],
                         ah0, ah1, ah2, ah3, bl[4*ng+2], bl[4*ng+3]);
            }
            // pass lh
#pragma unroll
            for (int ng = 0; ng < 4; ng++) {
                mma_bf16(s[2*ng][0], s[2*ng][1], s[2*ng][2], s[2*ng][3],
                         al0, al1, al2, al3, bh[4*ng+0], bh[4*ng+1]);
                mma_bf16(s[2*ng+1][0], s[2*ng+1][1], s[2*ng+1][2], s[2*ng+1][3],
                         al0, al1, al2, al3, bh[4*ng+2], bh[4*ng+3]);
            }
        }

        // ---- scale + causal mask + online softmax ----
        const bool do_mask = (causal != 0) && (k0 + 63 > q0);
        float mx0 = -1e30f, mx1 = -1e30f;
#pragma unroll
        for (int nt = 0; nt < 8; nt++) {
            const int cg = k0 + nt * 8 + cb;
            float v0 = s[nt][0] * sm_scale, v1 = s[nt][1] * sm_scale;
            float v2 = s[nt][2] * sm_scale, v3 = s[nt][3] * sm_scale;
            if (do_mask) {
                if (cg     > rg0) v0 = -1e30f;
                if (cg + 1 > rg0) v1 = -1e30f;
                if (cg     > rg1) v2 = -1e30f;
                if (cg + 1 > rg1) v3 = -1e30f;
            }
            s[nt][0] = v0; s[nt][1] = v1; s[nt][2] = v2; s[nt][3] = v3;
            mx0 = fmaxf(mx0, fmaxf(v0, v1));
            mx1 = fmaxf(mx1, fmaxf(v2, v3));
        }
        mx0 = fmaxf(mx0, __shfl_xor_sync(0xffffffffu, mx0, 1));
        mx0 = fmaxf(mx0, __shfl_xor_sync(0xffffffffu, mx0, 2));
        mx1 = fmaxf(mx1, __shfl_xor_sync(0xffffffffu, mx1, 1));
        mx1 = fmaxf(mx1, __shfl_xor_sync(0xffffffffu, mx1, 2));

        const float mn0 = fmaxf(m0v, mx0), mn1 = fmaxf(m1v, mx1);
        const float alpha0 = __expf(m0v - mn0), alpha1 = __expf(m1v - mn1);
        float sum0 = 0.0f, sum1 = 0.0f;
#pragma unroll
        for (int nt = 0; nt < 8; nt++) {
            float p0 = __expf(s[nt][0] - mn0), p1 = __expf(s[nt][1] - mn0);
            float p2 = __expf(s[nt][2] - mn1), p3 = __expf(s[nt][3] - mn1);
            s[nt][0] = p0; s[nt][1] = p1; s[nt][2] = p2; s[nt][3] = p3;
            sum0 += p0 + p1; sum1 += p2 + p3;
        }
        sum0 += __shfl_xor_sync(0xffffffffu, sum0, 1);
        sum0 += __shfl_xor_sync(0xffffffffu, sum0, 2);
        sum1 += __shfl_xor_sync(0xffffffffu, sum1, 1);
        sum1 += __shfl_xor_sync(0xffffffffu, sum1, 2);
        l0 = l0 * alpha0 + sum0;
        l1 = l1 * alpha1 + sum1;
        m0v = mn0; m1v = mn1;

#pragma unroll
        for (int nt = 0; nt < 16; nt++) {
            o[nt][0] *= alpha0; o[nt][1] *= alpha0;
            o[nt][2] *= alpha1; o[nt][3] *= alpha1;
        }

        // ---- P -> bf16 hi/lo A-fragments ----
        uint32_t ph[4][4], pl[4][4];
#pragma unroll
        for (int ks = 0; ks < 4; ks++) {
            pack_hilo(s[2*ks][0],   s[2*ks][1],   ph[ks][0], pl[ks][0]);
            pack_hilo(s[2*ks][2],   s[2*ks][3],   ph[ks][1], pl[ks][1]);
            pack_hilo(s[2*ks+1][0], s[2*ks+1][1], ph[ks][2], pl[ks][2]);
            pack_hilo(s[2*ks+1][2], s[2*ks+1][3], ph[ks][3], pl[ks][3]);
        }

        // ---- O += P V (bf16x3), n-groups in pairs for dependency spread ----
#pragma unroll
        for (int ks = 0; ks < 4; ks++) {
            const uint32_t vrow = (uint32_t)(ks * 16) + v_rbase;
            const uint32_t vxr  = (vrow & 7) << 4;
#pragma unroll
            for (int np = 0; np < 4; np++) {
                const int g0 = 2 * np, g1 = 2 * np + 1;
                const uint32_t voffA = vrow * 256 + (((uint32_t)(g0 * 32) + v_cb) ^ vxr);
                const uint32_t voffB = vrow * 256 + (((uint32_t)(g1 * 32) + v_cb) ^ vxr);
                uint32_t va[4], vb[4], wa[4], wb[4];
                LDSM_X4_T(va[0], va[1], va[2], va[3], sb + kvb + KVO_VHI + voffA);
                LDSM_X4_T(vb[0], vb[1], vb[2], vb[3], sb + kvb + KVO_VHI + voffB);
                LDSM_X4_T(wa[0], wa[1], wa[2], wa[3], sb + kvb + KVO_VLO + voffA);
                LDSM_X4_T(wb[0], wb[1], wb[2], wb[3], sb + kvb + KVO_VLO + voffB);
                // pass hh (4 independent)
                mma_bf16(o[2*g0][0], o[2*g0][1], o[2*g0][2], o[2*g0][3],
                         ph[ks][0], ph[ks][1], ph[ks][2], ph[ks][3], va[0], va[1]);
                mma_bf16(o[2*g0+1][0], o[2*g0+1][1], o[2*g0+1][2], o[2*g0+1][3],
                         ph[ks][0], ph[ks][1], ph[ks][2], ph[ks][3], va[2], va[3]);
                mma_bf16(o[2*g1][0], o[2*g1][1], o[2*g1][2], o[2*g1][3],
                         ph[ks][0], ph[ks][1], ph[ks][2], ph[ks][3], vb[0], vb[1]);
                mma_bf16(o[2*g1+1][0], o[2*g1+1][1], o[2*g1+1][2], o[2*g1+1][3],
                         ph[ks][0], ph[ks][1], ph[ks][2], ph[ks][3], vb[2], vb[3]);
                // pass hl
                mma_bf16(o[2*g0][0], o[2*g0][1], o[2*g0][2], o[2*g0][3],
                         ph[ks][0], ph[ks][1], ph[ks][2], ph[ks][3], wa[0], wa[1]);
                mma_bf16(o[2*g0+1][0], o[2*g0+1][1], o[2*g0+1][2], o[2*g0+1][3],
                         ph[ks][0], ph[ks][1], ph[ks][2], ph[ks][3], wa[2], wa[3]);
                mma_bf16(o[2*g1][0], o[2*g1][1], o[2*g1][2], o[2*g1][3],
                         ph[ks][0], ph[ks][1], ph[ks][2], ph[ks][3], wb[0], wb[1]);
                mma_bf16(o[2*g1+1][0], o[2*g1+1][1], o[2*g1+1][2], o[2*g1+1][3],
                         ph[ks][0], ph[ks][1], ph[ks][2], ph[ks][3], wb[2], wb[3]);
                // pass lh
                mma_bf16(o[2*g0][0], o[2*g0][1], o[2*g0][2], o[2*g0][3],
                         pl[ks][0], pl[ks][1], pl[ks][2], pl[ks][3], va[0], va[1]);
                mma_bf16(o[2*g0+1][0], o[2*g0+1][1], o[2*g0+1][2], o[2*g0+1][3],
                         pl[ks][0], pl[ks][1], pl[ks][2], pl[ks][3], va[2], va[3]);
                mma_bf16(o[2*g1][0], o[2*g1][1], o[2*g1][2], o[2*g1][3],
                         pl[ks][0], pl[ks][1], pl[ks][2], pl[ks][3], vb[0], vb[1]);
                mma_bf16(o[2*g1+1][0], o[2*g1+1][1], o[2*g1+1][2], o[2*g1+1][3],
                         pl[ks][0], pl[ks][1], pl[ks][2], pl[ks][3], vb[2], vb[3]);
            }
        }
    }

    // ---- epilogue ----
    const float inv0 = 1.0f / l0, inv1 = 1.0f / l1;
#pragma unroll
    for (int nt = 0; nt < 16; nt++) {
        const int col = h * HDIM + nt * 8 + cb;
        uint32_t hA, lA, hB, lB;
        pack_hilo(o[nt][0] * inv0, o[nt][1] * inv0, hA, lA);
        pack_hilo(o[nt][2] * inv1, o[nt][3] * inv1, hB, lB);
        *(uint32_t*)(g_ohi + (size_t)rg0 * D_MODEL + col) = hA;
        *(uint32_t*)(g_olo + (size_t)rg0 * D_MODEL + col) = lA;
        *(uint32_t*)(g_ohi + (size_t)rg1 * D_MODEL + col) = hB;
        *(uint32_t*)(g_olo + (size_t)rg1 * D_MODEL + col) = lB;
    }
}

// ---------------------------------------------------------------------------
// Launch
// ---------------------------------------------------------------------------
extern "C" void kernel_launch(void* const* d_in, const int* in_sizes, int n_in,
                              void* d_out, int out_size)
{
    const float* x  = (const float*)d_in[0];
    const float* wq = (const float*)d_in[1];
    const float* wk = (const float*)d_in[2];
    const float* wv = (const float*)d_in[3];
    const float* wo = (const float*)d_in[4];
    const int* causal = (const int*)d_in[5];
    float* out = (float*)d_out;

    __nv_bfloat16 *xhi, *xlo, *ohi, *olo;
    __nv_bfloat16 *qhi, *qlo, *khi, *klo, *vhi, *vlo;
    __nv_bfloat16 *wqh, *wql, *wkh, *wkl, *wvh, *wvl, *woh, *wol;
    cudaGetSymbolAddress((void**)&xhi, g_xhi);  cudaGetSymbolAddress((void**)&xlo, g_xlo);
    cudaGetSymbolAddress((void**)&ohi, g_ohi);  cudaGetSymbolAddress((void**)&olo, g_olo);
    cudaGetSymbolAddress((void**)&qhi, g_qhi);  cudaGetSymbolAddress((void**)&qlo, g_qlo);
    cudaGetSymbolAddress((void**)&khi, g_khi);  cudaGetSymbolAddress((void**)&klo, g_klo);
    cudaGetSymbolAddress((void**)&vhi, g_vhi);  cudaGetSymbolAddress((void**)&vlo, g_vlo);
    cudaGetSymbolAddress((void**)&wqh, g_wqhi); cudaGetSymbolAddress((void**)&wql, g_wqlo);
    cudaGetSymbolAddress((void**)&wkh, g_wkhi); cudaGetSymbolAddress((void**)&wkl, g_wklo);
    cudaGetSymbolAddress((void**)&wvh, g_wvhi); cudaGetSymbolAddress((void**)&wvl, g_wvlo);
    cudaGetSymbolAddress((void**)&woh, g_wohi); cudaGetSymbolAddress((void**)&wol, g_wolo);

    const int nx4 = S_LEN * D_MODEL / 4;
    const int nw4 = D_MODEL * D_MODEL / 4;

    split_kernel<<<nx4 / 256, 256>>>((const float4*)x, (__nv_bfloat162*)xhi, (__nv_bfloat162*)xlo, nx4);
    split_w_kernel<<<dim3(nw4 / 256, 4), 256>>>(
        (const float4*)wq, (const float4*)wk, (const float4*)wv, (const float4*)wo,
        (__nv_bfloat162*)wqh, (__nv_bfloat162*)wql,
        (__nv_bfloat162*)wkh, (__nv_bfloat162*)wkl,
        (__nv_bfloat162*)wvh, (__nv_bfloat162*)wvl,
        (__nv_bfloat162*)woh, (__nv_bfloat162*)wol, nw4);

    cudaFuncSetAttribute(gemm_mma_kernel<true>,  cudaFuncAttributeMaxDynamicSharedMemorySize, GEMM_SMEM);
    cudaFuncSetAttribute(gemm_mma_kernel<false>, cudaFuncAttributeMaxDynamicSharedMemorySize, GEMM_SMEM);
    dim3 gqkv(D_MODEL / 128, S_LEN / 128, 3);
    gemm_mma_kernel<true><<<gqkv, 256, GEMM_SMEM>>>(
        xhi, xlo, wqh, wql, wkh, wkl, wvh, wvl,
        nullptr, qhi, qlo, khi, klo, vhi, vlo);

    cudaFuncSetAttribute(attn_mma_kernel, cudaFuncAttributeMaxDynamicSharedMemorySize, ATT_SMEM);
    attn_mma_kernel<<<dim3(S_LEN / 128, NHEADS), 256, ATT_SMEM>>>(causal);

    dim3 gout(D_MODEL / 128, S_LEN / 128, 1);
    gemm_mma_kernel<false><<<gout, 256, GEMM_SMEM>>>(
        ohi, olo, woh, wol, woh, wol, woh, wol,
        out, nullptr, nullptr, nullptr, nullptr, nullptr, nullptr);
}